// round 8
// baseline (speedup 1.0000x reference)
#include <cuda_runtime.h>
#include <math.h>
#include <cstdint>

#define NN 8192
#define FF 256
#define DD 64
#define KH 2
#define JSPLIT 4

// ---------------- scratch (static device globals; no allocation) -------------
__device__ float g_HW [KH*NN*DD];     // [k][n][d]
__device__ float g_e1 [KH*NN];
__device__ float g_p1 [KH*NN];        // exp(e1)
__device__ float g_p51[KH*NN];        // exp(0.2 e1)
__device__ float4 g_ip [KH*NN];       // {e2, p2=exp(e2), p52=exp(0.2 e2), 0}
__device__ float4 g_jp [KH*NN];       // {e1, q1=p1/Z, q5=p51/Z, 0}
__device__ unsigned g_mask[NN*(NN/32)];  // bitpacked A, row-major [j][i/32]
__device__ float g_part[JSPLIT*KH*NN*DD]; // partial outputs [s][k][i][d]

// ---------------- small PTX helpers (plain sm_80+ PTX) ----------------------
__device__ __forceinline__ unsigned f2tf32(float f) {
    unsigned r;
    asm("cvt.rna.tf32.f32 %0, %1;" : "=r"(r) : "f"(f));
    return r;
}
__device__ __forceinline__ void mma_tf32(float* d, const unsigned* a, const unsigned* bf) {
    asm volatile(
        "mma.sync.aligned.m16n8k8.row.col.f32.tf32.tf32.f32 "
        "{%0,%1,%2,%3}, {%4,%5,%6,%7}, {%8,%9}, {%0,%1,%2,%3};"
        : "+f"(d[0]), "+f"(d[1]), "+f"(d[2]), "+f"(d[3])
        : "r"(a[0]), "r"(a[1]), "r"(a[2]), "r"(a[3]), "r"(bf[0]), "r"(bf[1]));
}

// ---------------- kernel 1: HW[k][n][d] = sum_f H[n][f] W[k][f][d] ----------
__global__ void k_hw(const float* __restrict__ H, const float* __restrict__ W) {
    __shared__ float Ws[64][128];
    __shared__ float Hs[32][64];
    const int tid = threadIdx.x;
    const int tx = tid & 31;
    const int ty = tid >> 5;
    const int n0 = blockIdx.x * 32;

    float acc[4][4];
#pragma unroll
    for (int a = 0; a < 4; a++)
#pragma unroll
        for (int b = 0; b < 4; b++) acc[a][b] = 0.f;

    for (int fc = 0; fc < FF; fc += 64) {
#pragma unroll
        for (int q = 0; q < 8; q++) {
            int idx = q * 256 + tid;
            int kk = idx >> 5, c4 = idx & 31;
            int c = c4 * 4;
            int k = c >> 6, d = c & 63;
            float4 v = *(const float4*)(W + k * (FF * DD) + (fc + kk) * DD + d);
            *(float4*)(&Ws[kk][c]) = v;
        }
#pragma unroll
        for (int q = 0; q < 2; q++) {
            int idx = q * 256 + tid;
            int r = idx >> 4, k4 = idx & 15;
            float4 v = *(const float4*)(H + (n0 + r) * FF + fc + k4 * 4);
            *(float4*)(&Hs[r][k4 * 4]) = v;
        }
        __syncthreads();
#pragma unroll 8
        for (int kk = 0; kk < 64; kk++) {
            float4 bv = *(const float4*)(&Ws[kk][tx * 4]);
            float a0 = Hs[ty * 4 + 0][kk];
            float a1 = Hs[ty * 4 + 1][kk];
            float a2 = Hs[ty * 4 + 2][kk];
            float a3 = Hs[ty * 4 + 3][kk];
            acc[0][0] += a0 * bv.x; acc[0][1] += a0 * bv.y; acc[0][2] += a0 * bv.z; acc[0][3] += a0 * bv.w;
            acc[1][0] += a1 * bv.x; acc[1][1] += a1 * bv.y; acc[1][2] += a1 * bv.z; acc[1][3] += a1 * bv.w;
            acc[2][0] += a2 * bv.x; acc[2][1] += a2 * bv.y; acc[2][2] += a2 * bv.z; acc[2][3] += a2 * bv.w;
            acc[3][0] += a3 * bv.x; acc[3][1] += a3 * bv.y; acc[3][2] += a3 * bv.z; acc[3][3] += a3 * bv.w;
        }
        __syncthreads();
    }
    const int c = tx * 4;
    const int k = c >> 6, d = c & 63;
#pragma unroll
    for (int s = 0; s < 4; s++) {
        int n = n0 + ty * 4 + s;
        float4 o = make_float4(acc[s][0], acc[s][1], acc[s][2], acc[s][3]);
        *(float4*)(g_HW + (k * NN + n) * DD + d) = o;
    }
}

// ------- kernel 2: e1/e2 per (k,n) + exp tables (packed) --------------------
__global__ void k_e(const float* __restrict__ a1, const float* __restrict__ a2) {
    __shared__ float a1s[128], a2s[128];
    const int tid = threadIdx.x;
    if (tid < 128) a1s[tid] = a1[tid];
    else           a2s[tid - 128] = a2[tid - 128];
    __syncthreads();
    const int t = blockIdx.x * 256 + tid;     // t = k*8192 + n
    const int k = t >> 13;
    const float* hw = g_HW + (size_t)t * DD;
    const float* A1 = a1s + k * 64;
    const float* A2 = a2s + k * 64;
    float e1 = 0.f, e2 = 0.f;
#pragma unroll
    for (int d4 = 0; d4 < 16; d4++) {
        float4 h = *(const float4*)(hw + d4 * 4);
        e1 += h.x * A1[d4 * 4 + 0] + h.y * A1[d4 * 4 + 1] + h.z * A1[d4 * 4 + 2] + h.w * A1[d4 * 4 + 3];
        e2 += h.x * A2[d4 * 4 + 0] + h.y * A2[d4 * 4 + 1] + h.z * A2[d4 * 4 + 2] + h.w * A2[d4 * 4 + 3];
    }
    g_e1[t]  = e1;
    g_p1[t]  = expf(e1);
    g_p51[t] = expf(0.2f * e1);
    g_ip[t]  = make_float4(e2, expf(e2), expf(0.2f * e2), 0.f);
}

// ------- kernel 3: softmax denominators Z + bitpack A -----------------------
__global__ void k_z(const int* __restrict__ A) {
    __shared__ float red[32][8];
    const int tid = threadIdx.x;
    const int lane = tid & 31, wrp = tid >> 5;
    const int j0 = blockIdx.x * 8;

    float e1r[8][2];
#pragma unroll
    for (int j = 0; j < 8; j++) {
        e1r[j][0] = g_e1[j0 + j];
        e1r[j][1] = g_e1[NN + j0 + j];
    }
    float sums[8][2][2];
#pragma unroll
    for (int j = 0; j < 8; j++)
#pragma unroll
        for (int k = 0; k < 2; k++) { sums[j][k][0] = 0.f; sums[j][k][1] = 0.f; }

    for (int ci = 0; ci < 32; ci++) {
        const int col = ci * 256 + tid;
        const float4 ip0 = g_ip[col];
        const float4 ip1 = g_ip[NN + col];
#pragma unroll
        for (int j = 0; j < 8; j++) {
            int a = A[(size_t)(j0 + j) * NN + col];
            unsigned bal = __ballot_sync(0xffffffffu, a != 0);
            if (lane == 0) g_mask[(j0 + j) * (NN / 32) + ci * 8 + wrp] = bal;
            if (a != 0) {
                float s0 = e1r[j][0] + ip0.x;
                if (s0 >= 0.f) sums[j][0][0] += ip0.y; else sums[j][0][1] += ip0.z;
                float s1 = e1r[j][1] + ip1.x;
                if (s1 >= 0.f) sums[j][1][0] += ip1.y; else sums[j][1][1] += ip1.z;
            }
        }
    }
#pragma unroll
    for (int v = 0; v < 32; v++) {
        int j = v >> 2, k = (v >> 1) & 1, tp = v & 1;
        float val = sums[j][k][tp];
        val += __shfl_down_sync(0xffffffffu, val, 16);
        val += __shfl_down_sync(0xffffffffu, val, 8);
        val += __shfl_down_sync(0xffffffffu, val, 4);
        val += __shfl_down_sync(0xffffffffu, val, 2);
        val += __shfl_down_sync(0xffffffffu, val, 1);
        if (lane == 0) red[v][wrp] = val;
    }
    __syncthreads();
    if (tid < 16) {
        int j = tid >> 1, k = tid & 1;
        float s0 = 0.f, s5 = 0.f;
#pragma unroll
        for (int w = 0; w < 8; w++) {
            s0 += red[(j * 2 + k) * 2 + 0][w];
            s5 += red[(j * 2 + k) * 2 + 1][w];
        }
        int gi = k * NN + j0 + j;
        float p1 = g_p1[gi], p51 = g_p51[gi];
        float rZ = 1.0f / (p1 * s0 + p51 * s5);
        g_jp[gi] = make_float4(g_e1[gi], p1 * rZ, p51 * rZ, 0.f);
    }
}

// ------- kernel 4 (mma.sync tf32, m32n32 warps, pipelined, j-split): --------
// CTA (bx, kh, s): i-tile bx*64, head kh, j-range split s. 4 warps: warp w
// owns m32 (mi2=w&1) x n32 (nh=w>>1); B frags reused across the two m16
// halves, halving B LDS traffic vs m16n64.
__global__ void __launch_bounds__(128) k_out_mma(float* __restrict__ part) {
    __shared__ unsigned Bs[2][64][36];      // tf32 bits, [d][j], stride 36
    __shared__ float4   jtab[2][32];        // {e1, q1, q5, -}
    __shared__ unsigned maskt[2][32][2];    // [j][word]

    const int tid  = threadIdx.x;
    const int wid  = tid >> 5;
    const int lane = tid & 31;
    const int kh   = blockIdx.y;
    const int spl  = blockIdx.z;
    const int i0   = blockIdx.x * 64;
    const int kbase = kh * NN;
    const int mrow0 = i0 >> 5;
    const int jt0  = spl * (NN / 32 / JSPLIT);
    const int jt1  = jt0 + (NN / 32 / JSPLIT);

    const int mi2 = wid & 1;            // m32 half (i rows mi2*32..+31)
    const int nh  = wid >> 1;           // n32 half (d cols nh*32..+31)
    const int rr = lane >> 2;           // 0..7
    const int cc = lane & 3;            // 0..3

    // per-lane i constants: [mb][h] -> i = i0 + mi2*32 + mb*16 + h*8 + rr
    float4 ipc[2][2];
#pragma unroll
    for (int mb = 0; mb < 2; mb++)
#pragma unroll
        for (int h = 0; h < 2; h++)
            ipc[mb][h] = g_ip[kbase + i0 + mi2 * 32 + mb * 16 + h * 8 + rr];

    const int bj = tid & 31;
    const int d0 = (tid >> 5) * 16;
    const float4* bsrc_base = (const float4*)(g_HW + (kbase + bj) * DD + d0);

    const int mjj = (tid - 32) >> 1;    // valid for tid in [32,96): 0..31
    const int mword = tid & 1;

    float4 rB[4];
    float4 rJ;
    unsigned rM = 0;

#define LDG_TILE(JT) do {                                                        \
    const int j0_ = (JT) * 32;                                                   \
    const float4* s_ = bsrc_base + j0_ * (DD / 4);                               \
    rB[0] = s_[0]; rB[1] = s_[1]; rB[2] = s_[2]; rB[3] = s_[3];                  \
    if (tid < 32)      rJ = g_jp[kbase + j0_ + tid];                             \
    else if (tid < 96) rM = g_mask[(j0_ + mjj) * (NN / 32) + mrow0 + mword];     \
} while (0)

#define STS_TILE(BUF) do {                                                       \
    float vv[16];                                                                \
    *(float4*)(vv + 0)  = rB[0]; *(float4*)(vv + 4)  = rB[1];                    \
    *(float4*)(vv + 8)  = rB[2]; *(float4*)(vv + 12) = rB[3];                    \
    _Pragma("unroll")                                                            \
    for (int s = 0; s < 16; s++) Bs[BUF][d0 + s][bj] = f2tf32(vv[s]);            \
    if (tid < 32)      jtab[BUF][tid] = rJ;                                      \
    else if (tid < 96) maskt[BUF][mjj][mword] = rM;                              \
} while (0)

    float acc[2][4][4];
#pragma unroll
    for (int mb = 0; mb < 2; mb++)
#pragma unroll
        for (int nb = 0; nb < 4; nb++)
#pragma unroll
            for (int q = 0; q < 4; q++) acc[mb][nb][q] = 0.f;

    LDG_TILE(jt0);
    STS_TILE(0);
    __syncthreads();

    for (int jt = jt0; jt < jt1; jt++) {
        const int bf = (jt - jt0) & 1;
        if (jt + 1 < jt1) LDG_TILE(jt + 1);

#pragma unroll
        for (int kb = 0; kb < 4; kb++) {
            const int jb = kb * 8;
            const float4 jv1 = jtab[bf][jb + cc];
            const float4 jv2 = jtab[bf][jb + cc + 4];
            const unsigned mw1 = maskt[bf][jb + cc][mi2];
            const unsigned mw2 = maskt[bf][jb + cc + 4][mi2];

            unsigned afr[2][4];
#pragma unroll
            for (int mb = 0; mb < 2; mb++) {
                const int bp = mb * 16 + rr;
                float s;
                s = jv1.x + ipc[mb][0].x;
                afr[mb][0] = f2tf32(((mw1 >> bp) & 1u)
                    ? (s >= 0.f ? jv1.y * ipc[mb][0].y : jv1.z * ipc[mb][0].z) : 0.f);
                s = jv1.x + ipc[mb][1].x;
                afr[mb][1] = f2tf32(((mw1 >> (bp + 8)) & 1u)
                    ? (s >= 0.f ? jv1.y * ipc[mb][1].y : jv1.z * ipc[mb][1].z) : 0.f);
                s = jv2.x + ipc[mb][0].x;
                afr[mb][2] = f2tf32(((mw2 >> bp) & 1u)
                    ? (s >= 0.f ? jv2.y * ipc[mb][0].y : jv2.z * ipc[mb][0].z) : 0.f);
                s = jv2.x + ipc[mb][1].x;
                afr[mb][3] = f2tf32(((mw2 >> (bp + 8)) & 1u)
                    ? (s >= 0.f ? jv2.y * ipc[mb][1].y : jv2.z * ipc[mb][1].z) : 0.f);
            }

#pragma unroll
            for (int nb = 0; nb < 4; nb++) {
                unsigned bfr[2];
                bfr[0] = Bs[bf][nh * 32 + nb * 8 + rr][jb + cc];
                bfr[1] = Bs[bf][nh * 32 + nb * 8 + rr][jb + cc + 4];
                mma_tf32(acc[0][nb], afr[0], bfr);
                mma_tf32(acc[1][nb], afr[1], bfr);
            }
        }

        if (jt + 1 < jt1) STS_TILE(bf ^ 1);
        __syncthreads();
    }

    // epilogue: write raw partials to g_part[spl][kh][i][d]
    float* pbase = part + ((size_t)(spl * KH + kh) * NN) * DD;
#pragma unroll
    for (int mb = 0; mb < 2; mb++) {
        const int ilo = i0 + mi2 * 32 + mb * 16 + rr;
#pragma unroll
        for (int nb = 0; nb < 4; nb++) {
            int col = nh * 32 + nb * 8 + 2 * cc;
            *(float2*)(pbase + (size_t)ilo * DD + col) =
                make_float2(acc[mb][nb][0], acc[mb][nb][1]);
            *(float2*)(pbase + (size_t)(ilo + 8) * DD + col) =
                make_float2(acc[mb][nb][2], acc[mb][nb][3]);
        }
    }
#undef LDG_TILE
#undef STS_TILE
}

// ------- kernel 5: reduce partials + bias + relu ----------------------------
__global__ void k_fin(const float* __restrict__ bias, float* __restrict__ out) {
    const int t = blockIdx.x * 256 + threadIdx.x;   // float4 id over [NN][K*D]
    const int d4 = t & 31;            // 0..31 (float4 within 128-float row)
    const int i  = t >> 5;
    const int kh = d4 >> 4;           // head
    const int dd4 = d4 & 15;          // float4 within head (d = dd4*4)
    const size_t pidx = (((size_t)kh * NN + i) * DD + dd4 * 4) / 4;

    const float4* P = (const float4*)g_part;
    const size_t stride4 = (size_t)KH * NN * DD / 4;
    float4 s0 = P[pidx];
    float4 s1 = P[pidx + stride4];
    float4 s2 = P[pidx + 2 * stride4];
    float4 s3 = P[pidx + 3 * stride4];
    float4 bv = *(const float4*)(bias + kh * DD + dd4 * 4);
    float4 o;
    o.x = fmaxf((s0.x + s1.x) + (s2.x + s3.x) + bv.x, 0.f);
    o.y = fmaxf((s0.y + s1.y) + (s2.y + s3.y) + bv.y, 0.f);
    o.z = fmaxf((s0.z + s1.z) + (s2.z + s3.z) + bv.z, 0.f);
    o.w = fmaxf((s0.w + s1.w) + (s2.w + s3.w) + bv.w, 0.f);
    ((float4*)out)[t] = o;
}

// ---------------------------------------------------------------------------
extern "C" void kernel_launch(void* const* d_in, const int* in_sizes, int n_in,
                              void* d_out, int out_size) {
    const float* H  = (const float*)d_in[0];   // [8192,256]
    const int*   A  = (const int*)  d_in[1];   // [8192,8192]
    const float* W  = (const float*)d_in[2];   // [2,256,64]
    const float* b  = (const float*)d_in[3];   // [2,64]
    const float* a1 = (const float*)d_in[4];   // [2,64]
    const float* a2 = (const float*)d_in[5];   // [2,64]
    float* out = (float*)d_out;                // [8192,128]

    float* part;
    cudaGetSymbolAddress((void**)&part, g_part);

    k_hw <<<NN / 32, 256>>>(H, W);
    k_e  <<<(KH * NN) / 256, 256>>>(a1, a2);
    k_z  <<<NN / 8, 256>>>(A);
    k_out_mma<<<dim3(NN / 64, KH, JSPLIT), 128>>>(part);
    k_fin<<<(NN * KH * DD / 4) / 256, 256>>>(b, out);
}

// round 9
// speedup vs baseline: 1.4532x; 1.4532x over previous
#include <cuda_runtime.h>
#include <math.h>
#include <cstdint>

#define NN 8192
#define FF 256
#define DD 64
#define KH 2
#define JSPLIT 4

// ---------------- scratch (static device globals; no allocation) -------------
__device__ float g_HW [KH*NN*DD];     // [k][n][d]
__device__ float g_e1 [KH*NN];
__device__ float g_p1 [KH*NN];        // exp(e1)
__device__ float g_p51[KH*NN];        // exp(0.2 e1)
__device__ float4 g_ip [KH*NN];       // {e2, p2=exp(e2), p52=exp(0.2 e2), 0}
__device__ float4 g_jp [KH*NN];       // {e1, q1=p1/Z, q5=p51/Z, 0}
__device__ unsigned g_mask[NN*(NN/32)];  // bitpacked A, row-major [j][i/32]
__device__ float g_part[JSPLIT*KH*NN*DD]; // partial outputs [s][k][i][d]

// ---------------- small PTX helpers (plain sm_80+ PTX) ----------------------
__device__ __forceinline__ unsigned f2tf32(float f) {
    unsigned r;
    asm("cvt.rna.tf32.f32 %0, %1;" : "=r"(r) : "f"(f));
    return r;
}
__device__ __forceinline__ void mma_tf32(float* d, const unsigned* a, const unsigned* bf) {
    asm volatile(
        "mma.sync.aligned.m16n8k8.row.col.f32.tf32.tf32.f32 "
        "{%0,%1,%2,%3}, {%4,%5,%6,%7}, {%8,%9}, {%0,%1,%2,%3};"
        : "+f"(d[0]), "+f"(d[1]), "+f"(d[2]), "+f"(d[3])
        : "r"(a[0]), "r"(a[1]), "r"(a[2]), "r"(a[3]), "r"(bf[0]), "r"(bf[1]));
}

// ---------------- kernel 1: HW[k][n][d] = sum_f H[n][f] W[k][f][d] ----------
__global__ void k_hw(const float* __restrict__ H, const float* __restrict__ W) {
    __shared__ float Ws[64][128];
    __shared__ float Hs[32][64];
    const int tid = threadIdx.x;
    const int tx = tid & 31;
    const int ty = tid >> 5;
    const int n0 = blockIdx.x * 32;

    float acc[4][4];
#pragma unroll
    for (int a = 0; a < 4; a++)
#pragma unroll
        for (int b = 0; b < 4; b++) acc[a][b] = 0.f;

    for (int fc = 0; fc < FF; fc += 64) {
#pragma unroll
        for (int q = 0; q < 8; q++) {
            int idx = q * 256 + tid;
            int kk = idx >> 5, c4 = idx & 31;
            int c = c4 * 4;
            int k = c >> 6, d = c & 63;
            float4 v = *(const float4*)(W + k * (FF * DD) + (fc + kk) * DD + d);
            *(float4*)(&Ws[kk][c]) = v;
        }
#pragma unroll
        for (int q = 0; q < 2; q++) {
            int idx = q * 256 + tid;
            int r = idx >> 4, k4 = idx & 15;
            float4 v = *(const float4*)(H + (n0 + r) * FF + fc + k4 * 4);
            *(float4*)(&Hs[r][k4 * 4]) = v;
        }
        __syncthreads();
#pragma unroll 8
        for (int kk = 0; kk < 64; kk++) {
            float4 bv = *(const float4*)(&Ws[kk][tx * 4]);
            float a0 = Hs[ty * 4 + 0][kk];
            float a1 = Hs[ty * 4 + 1][kk];
            float a2 = Hs[ty * 4 + 2][kk];
            float a3 = Hs[ty * 4 + 3][kk];
            acc[0][0] += a0 * bv.x; acc[0][1] += a0 * bv.y; acc[0][2] += a0 * bv.z; acc[0][3] += a0 * bv.w;
            acc[1][0] += a1 * bv.x; acc[1][1] += a1 * bv.y; acc[1][2] += a1 * bv.z; acc[1][3] += a1 * bv.w;
            acc[2][0] += a2 * bv.x; acc[2][1] += a2 * bv.y; acc[2][2] += a2 * bv.z; acc[2][3] += a2 * bv.w;
            acc[3][0] += a3 * bv.x; acc[3][1] += a3 * bv.y; acc[3][2] += a3 * bv.z; acc[3][3] += a3 * bv.w;
        }
        __syncthreads();
    }
    const int c = tx * 4;
    const int k = c >> 6, d = c & 63;
#pragma unroll
    for (int s = 0; s < 4; s++) {
        int n = n0 + ty * 4 + s;
        float4 o = make_float4(acc[s][0], acc[s][1], acc[s][2], acc[s][3]);
        *(float4*)(g_HW + (k * NN + n) * DD + d) = o;
    }
}

// ------- kernel 2: e1/e2 per (k,n) + exp tables (packed) --------------------
__global__ void k_e(const float* __restrict__ a1, const float* __restrict__ a2) {
    __shared__ float a1s[128], a2s[128];
    const int tid = threadIdx.x;
    if (tid < 128) a1s[tid] = a1[tid];
    else           a2s[tid - 128] = a2[tid - 128];
    __syncthreads();
    const int t = blockIdx.x * 256 + tid;     // t = k*8192 + n
    const int k = t >> 13;
    const float* hw = g_HW + (size_t)t * DD;
    const float* A1 = a1s + k * 64;
    const float* A2 = a2s + k * 64;
    float e1 = 0.f, e2 = 0.f;
#pragma unroll
    for (int d4 = 0; d4 < 16; d4++) {
        float4 h = *(const float4*)(hw + d4 * 4);
        e1 += h.x * A1[d4 * 4 + 0] + h.y * A1[d4 * 4 + 1] + h.z * A1[d4 * 4 + 2] + h.w * A1[d4 * 4 + 3];
        e2 += h.x * A2[d4 * 4 + 0] + h.y * A2[d4 * 4 + 1] + h.z * A2[d4 * 4 + 2] + h.w * A2[d4 * 4 + 3];
    }
    g_e1[t]  = e1;
    g_p1[t]  = expf(e1);
    g_p51[t] = expf(0.2f * e1);
    g_ip[t]  = make_float4(e2, expf(e2), expf(0.2f * e2), 0.f);
}

// ------- kernel 3: softmax denominators Z + bitpack A (BRANCHLESS) ----------
// CTA = 8 rows (j), 256 threads, column-per-thread. Inner loop is pure
// FSETP/FSEL/FFMA (no divergent branches).
__global__ void k_z(const int* __restrict__ A) {
    __shared__ float red[32][8];
    const int tid = threadIdx.x;
    const int lane = tid & 31, wrp = tid >> 5;
    const int j0 = blockIdx.x * 8;

    float e1r[8][2];
#pragma unroll
    for (int j = 0; j < 8; j++) {
        e1r[j][0] = g_e1[j0 + j];
        e1r[j][1] = g_e1[NN + j0 + j];
    }
    float sums[8][2][2];
#pragma unroll
    for (int j = 0; j < 8; j++)
#pragma unroll
        for (int k = 0; k < 2; k++) { sums[j][k][0] = 0.f; sums[j][k][1] = 0.f; }

    for (int ci = 0; ci < 32; ci++) {
        const int col = ci * 256 + tid;
        const float4 ip0 = g_ip[col];
        const float4 ip1 = g_ip[NN + col];
#pragma unroll
        for (int j = 0; j < 8; j++) {
            int a = A[(size_t)(j0 + j) * NN + col];
            unsigned bal = __ballot_sync(0xffffffffu, a != 0);
            if (lane == 0) g_mask[(j0 + j) * (NN / 32) + ci * 8 + wrp] = bal;
            float am = (a != 0) ? 1.0f : 0.0f;
            {
                float s = e1r[j][0] + ip0.x;
                bool pos = s >= 0.f;
                sums[j][0][0] += am * (pos ? ip0.y : 0.f);
                sums[j][0][1] += am * (pos ? 0.f : ip0.z);
            }
            {
                float s = e1r[j][1] + ip1.x;
                bool pos = s >= 0.f;
                sums[j][1][0] += am * (pos ? ip1.y : 0.f);
                sums[j][1][1] += am * (pos ? 0.f : ip1.z);
            }
        }
    }
#pragma unroll
    for (int v = 0; v < 32; v++) {
        int j = v >> 2, k = (v >> 1) & 1, tp = v & 1;
        float val = sums[j][k][tp];
        val += __shfl_down_sync(0xffffffffu, val, 16);
        val += __shfl_down_sync(0xffffffffu, val, 8);
        val += __shfl_down_sync(0xffffffffu, val, 4);
        val += __shfl_down_sync(0xffffffffu, val, 2);
        val += __shfl_down_sync(0xffffffffu, val, 1);
        if (lane == 0) red[v][wrp] = val;
    }
    __syncthreads();
    if (tid < 16) {
        int j = tid >> 1, k = tid & 1;
        float s0 = 0.f, s5 = 0.f;
#pragma unroll
        for (int w = 0; w < 8; w++) {
            s0 += red[(j * 2 + k) * 2 + 0][w];
            s5 += red[(j * 2 + k) * 2 + 1][w];
        }
        int gi = k * NN + j0 + j;
        float p1 = g_p1[gi], p51 = g_p51[gi];
        float rZ = 1.0f / (p1 * s0 + p51 * s5);
        g_jp[gi] = make_float4(g_e1[gi], p1 * rZ, p51 * rZ, 0.f);
    }
}

// ------- kernel 4 (mma.sync tf32, m16n64 warps, pipelined, j-split): --------
// (reverted to the round-7 version: best measured at 340us)
__global__ void __launch_bounds__(128) k_out_mma(float* __restrict__ part) {
    __shared__ unsigned Bs[2][64][36];      // tf32 bits, [d][j], stride 36
    __shared__ float4   jtab[2][32];        // {e1, q1, q5, -}
    __shared__ unsigned maskt[2][32][2];    // [j][word]

    const int tid  = threadIdx.x;
    const int wid  = tid >> 5;
    const int lane = tid & 31;
    const int kh   = blockIdx.y;
    const int spl  = blockIdx.z;
    const int i0   = blockIdx.x * 64;
    const int kbase = kh * NN;
    const int mrow0 = i0 >> 5;
    const int jt0  = spl * (NN / 32 / JSPLIT);     // 64 tiles per split
    const int jt1  = jt0 + (NN / 32 / JSPLIT);

    const int mi = wid;                 // m16 block 0..3
    const int rr = lane >> 2;           // 0..7
    const int cc = lane & 3;            // 0..3
    const int wsel = mi >> 1;           // mask word within tile
    const int bplo = (mi & 1) * 16 + rr;

    const float4 iplo = g_ip[kbase + i0 + mi * 16 + rr];
    const float4 iphi = g_ip[kbase + i0 + mi * 16 + rr + 8];

    const int bj = tid & 31;
    const int d0 = (tid >> 5) * 16;
    const float4* bsrc_base = (const float4*)(g_HW + (kbase + bj) * DD + d0);

    const int mjj = (tid - 32) >> 1;    // valid for tid in [32,96): 0..31
    const int mword = tid & 1;

    float4 rB[4];
    float4 rJ;
    unsigned rM = 0;

#define LDG_TILE(JT) do {                                                        \
    const int j0_ = (JT) * 32;                                                   \
    const float4* s_ = bsrc_base + j0_ * (DD / 4);                               \
    rB[0] = s_[0]; rB[1] = s_[1]; rB[2] = s_[2]; rB[3] = s_[3];                  \
    if (tid < 32)      rJ = g_jp[kbase + j0_ + tid];                             \
    else if (tid < 96) rM = g_mask[(j0_ + mjj) * (NN / 32) + mrow0 + mword];     \
} while (0)

#define STS_TILE(BUF) do {                                                       \
    float vv[16];                                                                \
    *(float4*)(vv + 0)  = rB[0]; *(float4*)(vv + 4)  = rB[1];                    \
    *(float4*)(vv + 8)  = rB[2]; *(float4*)(vv + 12) = rB[3];                    \
    _Pragma("unroll")                                                            \
    for (int s = 0; s < 16; s++) Bs[BUF][d0 + s][bj] = f2tf32(vv[s]);            \
    if (tid < 32)      jtab[BUF][tid] = rJ;                                      \
    else if (tid < 96) maskt[BUF][mjj][mword] = rM;                              \
} while (0)

    float acc[8][4];
#pragma unroll
    for (int nb = 0; nb < 8; nb++)
#pragma unroll
        for (int q = 0; q < 4; q++) acc[nb][q] = 0.f;

    LDG_TILE(jt0);
    STS_TILE(0);
    __syncthreads();

    for (int jt = jt0; jt < jt1; jt++) {
        const int bf = (jt - jt0) & 1;
        if (jt + 1 < jt1) LDG_TILE(jt + 1);

#pragma unroll
        for (int kb = 0; kb < 4; kb++) {
            const int jb = kb * 8;
            const float4 jv1 = jtab[bf][jb + cc];
            const float4 jv2 = jtab[bf][jb + cc + 4];
            const unsigned t1 = maskt[bf][jb + cc][wsel] >> bplo;
            const unsigned t2 = maskt[bf][jb + cc + 4][wsel] >> bplo;

            unsigned afr[4];
            float s;
            s = jv1.x + iplo.x;
            afr[0] = f2tf32((t1 & 1u)   ? (s >= 0.f ? jv1.y * iplo.y : jv1.z * iplo.z) : 0.f);
            s = jv1.x + iphi.x;
            afr[1] = f2tf32((t1 & 256u) ? (s >= 0.f ? jv1.y * iphi.y : jv1.z * iphi.z) : 0.f);
            s = jv2.x + iplo.x;
            afr[2] = f2tf32((t2 & 1u)   ? (s >= 0.f ? jv2.y * iplo.y : jv2.z * iplo.z) : 0.f);
            s = jv2.x + iphi.x;
            afr[3] = f2tf32((t2 & 256u) ? (s >= 0.f ? jv2.y * iphi.y : jv2.z * iphi.z) : 0.f);

#pragma unroll
            for (int nb = 0; nb < 8; nb++) {
                unsigned bfr[2];
                bfr[0] = Bs[bf][nb * 8 + rr][jb + cc];
                bfr[1] = Bs[bf][nb * 8 + rr][jb + cc + 4];
                mma_tf32(acc[nb], afr, bfr);
            }
        }

        if (jt + 1 < jt1) STS_TILE(bf ^ 1);
        __syncthreads();
    }

    // epilogue: write raw partials to g_part[spl][kh][i][d]
    float* pbase = part + ((size_t)(spl * KH + kh) * NN) * DD;
    const int ilo = i0 + mi * 16 + rr;
#pragma unroll
    for (int nb = 0; nb < 8; nb++) {
        int col = nb * 8 + 2 * cc;
        *(float2*)(pbase + (size_t)ilo * DD + col) = make_float2(acc[nb][0], acc[nb][1]);
        *(float2*)(pbase + (size_t)(ilo + 8) * DD + col) = make_float2(acc[nb][2], acc[nb][3]);
    }
#undef LDG_TILE
#undef STS_TILE
}

// ------- kernel 5: reduce partials + bias + relu ----------------------------
__global__ void k_fin(const float* __restrict__ bias, float* __restrict__ out) {
    const int t = blockIdx.x * 256 + threadIdx.x;   // float4 id over [NN][K*D]
    const int d4 = t & 31;            // 0..31 (float4 within 128-float row)
    const int i  = t >> 5;
    const int kh = d4 >> 4;           // head
    const int dd4 = d4 & 15;          // float4 within head (d = dd4*4)
    const size_t pidx = (((size_t)kh * NN + i) * DD + dd4 * 4) / 4;

    const float4* P = (const float4*)g_part;
    const size_t stride4 = (size_t)KH * NN * DD / 4;
    float4 s0 = P[pidx];
    float4 s1 = P[pidx + stride4];
    float4 s2 = P[pidx + 2 * stride4];
    float4 s3 = P[pidx + 3 * stride4];
    float4 bv = *(const float4*)(bias + kh * DD + dd4 * 4);
    float4 o;
    o.x = fmaxf((s0.x + s1.x) + (s2.x + s3.x) + bv.x, 0.f);
    o.y = fmaxf((s0.y + s1.y) + (s2.y + s3.y) + bv.y, 0.f);
    o.z = fmaxf((s0.z + s1.z) + (s2.z + s3.z) + bv.z, 0.f);
    o.w = fmaxf((s0.w + s1.w) + (s2.w + s3.w) + bv.w, 0.f);
    ((float4*)out)[t] = o;
}

// ---------------------------------------------------------------------------
extern "C" void kernel_launch(void* const* d_in, const int* in_sizes, int n_in,
                              void* d_out, int out_size) {
    const float* H  = (const float*)d_in[0];   // [8192,256]
    const int*   A  = (const int*)  d_in[1];   // [8192,8192]
    const float* W  = (const float*)d_in[2];   // [2,256,64]
    const float* b  = (const float*)d_in[3];   // [2,64]
    const float* a1 = (const float*)d_in[4];   // [2,64]
    const float* a2 = (const float*)d_in[5];   // [2,64]
    float* out = (float*)d_out;                // [8192,128]

    float* part;
    cudaGetSymbolAddress((void**)&part, g_part);

    k_hw <<<NN / 32, 256>>>(H, W);
    k_e  <<<(KH * NN) / 256, 256>>>(a1, a2);
    k_z  <<<NN / 8, 256>>>(A);
    k_out_mma<<<dim3(NN / 64, KH, JSPLIT), 128>>>(part);
    k_fin<<<(NN * KH * DD / 4) / 256, 256>>>(b, out);
}

// round 10
// speedup vs baseline: 1.6320x; 1.1231x over previous
#include <cuda_runtime.h>
#include <math.h>
#include <cstdint>

#define NN 8192
#define FF 256
#define DD 64
#define KH 2
#define JSPLIT 4

// ---------------- scratch (static device globals; no allocation) -------------
__device__ float g_HW [KH*NN*DD];     // [k][n][d]
__device__ float g_e1 [KH*NN];
__device__ float g_p1 [KH*NN];        // exp(e1)
__device__ float g_p51[KH*NN];        // exp(0.2 e1)
__device__ float4 g_ip [KH*NN];       // {e2, p2=exp(e2), p52=exp(0.2 e2), 0}
__device__ float4 g_jp [KH*NN];       // {e1, q1=p1/Z, q5=p51/Z, 0}
__device__ unsigned g_mask[NN*(NN/32)];  // bitpacked A, row-major [j][i/32]
__device__ float g_part[JSPLIT*KH*NN*DD]; // partial outputs [s][k][i][d]

// ---------------- small PTX helpers (plain sm_80+ PTX) ----------------------
__device__ __forceinline__ unsigned pack_h2(float lo, float hi) {
    unsigned r;
    asm("cvt.rn.f16x2.f32 %0, %1, %2;" : "=r"(r) : "f"(hi), "f"(lo));
    return r;
}
__device__ __forceinline__ void mma_f16(float* d, const unsigned* a, const unsigned* bf) {
    asm volatile(
        "mma.sync.aligned.m16n8k16.row.col.f32.f16.f16.f32 "
        "{%0,%1,%2,%3}, {%4,%5,%6,%7}, {%8,%9}, {%0,%1,%2,%3};"
        : "+f"(d[0]), "+f"(d[1]), "+f"(d[2]), "+f"(d[3])
        : "r"(a[0]), "r"(a[1]), "r"(a[2]), "r"(a[3]), "r"(bf[0]), "r"(bf[1]));
}

// ---------------- kernel 1: HW[k][n][d] = sum_f H[n][f] W[k][f][d] ----------
__global__ void k_hw(const float* __restrict__ H, const float* __restrict__ W) {
    __shared__ float Ws[64][128];
    __shared__ float Hs[32][64];
    const int tid = threadIdx.x;
    const int tx = tid & 31;
    const int ty = tid >> 5;
    const int n0 = blockIdx.x * 32;

    float acc[4][4];
#pragma unroll
    for (int a = 0; a < 4; a++)
#pragma unroll
        for (int b = 0; b < 4; b++) acc[a][b] = 0.f;

    for (int fc = 0; fc < FF; fc += 64) {
#pragma unroll
        for (int q = 0; q < 8; q++) {
            int idx = q * 256 + tid;
            int kk = idx >> 5, c4 = idx & 31;
            int c = c4 * 4;
            int k = c >> 6, d = c & 63;
            float4 v = *(const float4*)(W + k * (FF * DD) + (fc + kk) * DD + d);
            *(float4*)(&Ws[kk][c]) = v;
        }
#pragma unroll
        for (int q = 0; q < 2; q++) {
            int idx = q * 256 + tid;
            int r = idx >> 4, k4 = idx & 15;
            float4 v = *(const float4*)(H + (n0 + r) * FF + fc + k4 * 4);
            *(float4*)(&Hs[r][k4 * 4]) = v;
        }
        __syncthreads();
#pragma unroll 8
        for (int kk = 0; kk < 64; kk++) {
            float4 bv = *(const float4*)(&Ws[kk][tx * 4]);
            float a0 = Hs[ty * 4 + 0][kk];
            float a1 = Hs[ty * 4 + 1][kk];
            float a2 = Hs[ty * 4 + 2][kk];
            float a3 = Hs[ty * 4 + 3][kk];
            acc[0][0] += a0 * bv.x; acc[0][1] += a0 * bv.y; acc[0][2] += a0 * bv.z; acc[0][3] += a0 * bv.w;
            acc[1][0] += a1 * bv.x; acc[1][1] += a1 * bv.y; acc[1][2] += a1 * bv.z; acc[1][3] += a1 * bv.w;
            acc[2][0] += a2 * bv.x; acc[2][1] += a2 * bv.y; acc[2][2] += a2 * bv.z; acc[2][3] += a2 * bv.w;
            acc[3][0] += a3 * bv.x; acc[3][1] += a3 * bv.y; acc[3][2] += a3 * bv.z; acc[3][3] += a3 * bv.w;
        }
        __syncthreads();
    }
    const int c = tx * 4;
    const int k = c >> 6, d = c & 63;
#pragma unroll
    for (int s = 0; s < 4; s++) {
        int n = n0 + ty * 4 + s;
        float4 o = make_float4(acc[s][0], acc[s][1], acc[s][2], acc[s][3]);
        *(float4*)(g_HW + (k * NN + n) * DD + d) = o;
    }
}

// ------- kernel 2: e1/e2 per (k,n) + exp tables (packed) --------------------
__global__ void k_e(const float* __restrict__ a1, const float* __restrict__ a2) {
    __shared__ float a1s[128], a2s[128];
    const int tid = threadIdx.x;
    if (tid < 128) a1s[tid] = a1[tid];
    else           a2s[tid - 128] = a2[tid - 128];
    __syncthreads();
    const int t = blockIdx.x * 256 + tid;     // t = k*8192 + n
    const int k = t >> 13;
    const float* hw = g_HW + (size_t)t * DD;
    const float* A1 = a1s + k * 64;
    const float* A2 = a2s + k * 64;
    float e1 = 0.f, e2 = 0.f;
#pragma unroll
    for (int d4 = 0; d4 < 16; d4++) {
        float4 h = *(const float4*)(hw + d4 * 4);
        e1 += h.x * A1[d4 * 4 + 0] + h.y * A1[d4 * 4 + 1] + h.z * A1[d4 * 4 + 2] + h.w * A1[d4 * 4 + 3];
        e2 += h.x * A2[d4 * 4 + 0] + h.y * A2[d4 * 4 + 1] + h.z * A2[d4 * 4 + 2] + h.w * A2[d4 * 4 + 3];
    }
    g_e1[t]  = e1;
    g_p1[t]  = expf(e1);
    g_p51[t] = expf(0.2f * e1);
    g_ip[t]  = make_float4(e2, expf(e2), expf(0.2f * e2), 0.f);
}

// ------- kernel 3: softmax denominators Z + bitpack A (branchless) ----------
__global__ void k_z(const int* __restrict__ A) {
    __shared__ float red[32][8];
    const int tid = threadIdx.x;
    const int lane = tid & 31, wrp = tid >> 5;
    const int j0 = blockIdx.x * 8;

    float e1r[8][2];
#pragma unroll
    for (int j = 0; j < 8; j++) {
        e1r[j][0] = g_e1[j0 + j];
        e1r[j][1] = g_e1[NN + j0 + j];
    }
    float sums[8][2][2];
#pragma unroll
    for (int j = 0; j < 8; j++)
#pragma unroll
        for (int k = 0; k < 2; k++) { sums[j][k][0] = 0.f; sums[j][k][1] = 0.f; }

    for (int ci = 0; ci < 32; ci++) {
        const int col = ci * 256 + tid;
        const float4 ip0 = g_ip[col];
        const float4 ip1 = g_ip[NN + col];
#pragma unroll
        for (int j = 0; j < 8; j++) {
            int a = A[(size_t)(j0 + j) * NN + col];
            unsigned bal = __ballot_sync(0xffffffffu, a != 0);
            if (lane == 0) g_mask[(j0 + j) * (NN / 32) + ci * 8 + wrp] = bal;
            float am = (a != 0) ? 1.0f : 0.0f;
            {
                float s = e1r[j][0] + ip0.x;
                bool pos = s >= 0.f;
                sums[j][0][0] += am * (pos ? ip0.y : 0.f);
                sums[j][0][1] += am * (pos ? 0.f : ip0.z);
            }
            {
                float s = e1r[j][1] + ip1.x;
                bool pos = s >= 0.f;
                sums[j][1][0] += am * (pos ? ip1.y : 0.f);
                sums[j][1][1] += am * (pos ? 0.f : ip1.z);
            }
        }
    }
#pragma unroll
    for (int v = 0; v < 32; v++) {
        int j = v >> 2, k = (v >> 1) & 1, tp = v & 1;
        float val = sums[j][k][tp];
        val += __shfl_down_sync(0xffffffffu, val, 16);
        val += __shfl_down_sync(0xffffffffu, val, 8);
        val += __shfl_down_sync(0xffffffffu, val, 4);
        val += __shfl_down_sync(0xffffffffu, val, 2);
        val += __shfl_down_sync(0xffffffffu, val, 1);
        if (lane == 0) red[v][wrp] = val;
    }
    __syncthreads();
    if (tid < 16) {
        int j = tid >> 1, k = tid & 1;
        float s0 = 0.f, s5 = 0.f;
#pragma unroll
        for (int w = 0; w < 8; w++) {
            s0 += red[(j * 2 + k) * 2 + 0][w];
            s5 += red[(j * 2 + k) * 2 + 1][w];
        }
        int gi = k * NN + j0 + j;
        float p1 = g_p1[gi], p51 = g_p51[gi];
        float rZ = 1.0f / (p1 * s0 + p51 * s5);
        g_jp[gi] = make_float4(g_e1[gi], p1 * rZ, p51 * rZ, 0.f);
    }
}

// ------- kernel 4 (mma.sync f16 m16n8k16, m16n64 warps, pipelined, j-split) -
// B staged as packed half2 {j even, j odd}: half the LDS bytes and half the
// MMA count of the tf32 version. A weights built in f32, packed to f16x2.
__global__ void __launch_bounds__(128) k_out_mma(float* __restrict__ part) {
    __shared__ unsigned Bs[2][64][20];      // half2 {2jj, 2jj+1}, [d][jj], stride 20
    __shared__ float4   jtab[2][32];        // {e1, q1, q5, -}
    __shared__ unsigned maskt[2][32][2];    // [j][word]

    const int tid  = threadIdx.x;
    const int lane = tid & 31;
    const int wid  = tid >> 5;
    const int kh   = blockIdx.y;
    const int spl  = blockIdx.z;
    const int i0   = blockIdx.x * 64;
    const int kbase = kh * NN;
    const int mrow0 = i0 >> 5;
    const int jt0  = spl * (NN / 32 / JSPLIT);     // 64 tiles per split
    const int jt1  = jt0 + (NN / 32 / JSPLIT);

    const int mi = wid;                 // m16 block 0..3
    const int rr = lane >> 2;           // 0..7
    const int cc = lane & 3;            // 0..3
    const int wsel = mi >> 1;           // mask word within tile
    const int bplo = (mi & 1) * 16 + rr;

    const float4 iplo = g_ip[kbase + i0 + mi * 16 + rr];
    const float4 iphi = g_ip[kbase + i0 + mi * 16 + rr + 8];

    // B-stage coords: thread handles j-pair p, 8 d values
    const int bp = tid & 15;            // j-pair 0..15
    const int d0 = (tid >> 4) * 8;      // 0,8,..,56
    const float* bsrc0 = g_HW + (size_t)(kbase + 2 * bp) * DD + d0;      // even j
    const float* bsrc1 = g_HW + (size_t)(kbase + 2 * bp + 1) * DD + d0;  // odd j

    const int mjj = (tid - 32) >> 1;    // valid for tid in [32,96): 0..31
    const int mword = tid & 1;

    float4 rB[4];                       // [0,1]=even j d0..d0+7, [2,3]=odd j
    float4 rJ;
    unsigned rM = 0;

#define LDG_TILE(JT) do {                                                        \
    const int j0_ = (JT) * 32;                                                   \
    const float* e_ = bsrc0 + (size_t)j0_ * DD;                                  \
    const float* o_ = bsrc1 + (size_t)j0_ * DD;                                  \
    rB[0] = *(const float4*)(e_);  rB[1] = *(const float4*)(e_ + 4);             \
    rB[2] = *(const float4*)(o_);  rB[3] = *(const float4*)(o_ + 4);             \
    if (tid < 32)      rJ = g_jp[kbase + j0_ + tid];                             \
    else if (tid < 96) rM = g_mask[(j0_ + mjj) * (NN / 32) + mrow0 + mword];     \
} while (0)

#define STS_TILE(BUF) do {                                                       \
    float ev[8], od[8];                                                          \
    *(float4*)(ev + 0) = rB[0]; *(float4*)(ev + 4) = rB[1];                      \
    *(float4*)(od + 0) = rB[2]; *(float4*)(od + 4) = rB[3];                      \
    _Pragma("unroll")                                                            \
    for (int s = 0; s < 8; s++) Bs[BUF][d0 + s][bp] = pack_h2(ev[s], od[s]);     \
    if (tid < 32)      jtab[BUF][tid] = rJ;                                      \
    else if (tid < 96) maskt[BUF][mjj][mword] = rM;                              \
} while (0)

    float acc[8][4];
#pragma unroll
    for (int nb = 0; nb < 8; nb++)
#pragma unroll
        for (int q = 0; q < 4; q++) acc[nb][q] = 0.f;

    LDG_TILE(jt0);
    STS_TILE(0);
    __syncthreads();

    for (int jt = jt0; jt < jt1; jt++) {
        const int bf = (jt - jt0) & 1;
        if (jt + 1 < jt1) LDG_TILE(jt + 1);

#pragma unroll
        for (int kg = 0; kg < 2; kg++) {            // two k16 groups per 32-j tile
            const int jb = kg * 16;
            const int ja = jb + 2 * cc;             // j0
            const int jc = jb + 2 * cc + 8;         // j2
            const float4 jva = jtab[bf][ja];
            const float4 jvb = jtab[bf][ja + 1];
            const float4 jvc = jtab[bf][jc];
            const float4 jvd = jtab[bf][jc + 1];
            const unsigned ta = maskt[bf][ja][wsel]     >> bplo;
            const unsigned tb = maskt[bf][ja + 1][wsel] >> bplo;
            const unsigned tc = maskt[bf][jc][wsel]     >> bplo;
            const unsigned td = maskt[bf][jc + 1][wsel] >> bplo;

            float s;
            s = jva.x + iplo.x;
            float wa0 = (ta & 1u)   ? (s >= 0.f ? jva.y * iplo.y : jva.z * iplo.z) : 0.f;
            s = jva.x + iphi.x;
            float wa1 = (ta & 256u) ? (s >= 0.f ? jva.y * iphi.y : jva.z * iphi.z) : 0.f;
            s = jvb.x + iplo.x;
            float wb0 = (tb & 1u)   ? (s >= 0.f ? jvb.y * iplo.y : jvb.z * iplo.z) : 0.f;
            s = jvb.x + iphi.x;
            float wb1 = (tb & 256u) ? (s >= 0.f ? jvb.y * iphi.y : jvb.z * iphi.z) : 0.f;
            s = jvc.x + iplo.x;
            float wc0 = (tc & 1u)   ? (s >= 0.f ? jvc.y * iplo.y : jvc.z * iplo.z) : 0.f;
            s = jvc.x + iphi.x;
            float wc1 = (tc & 256u) ? (s >= 0.f ? jvc.y * iphi.y : jvc.z * iphi.z) : 0.f;
            s = jvd.x + iplo.x;
            float wd0 = (td & 1u)   ? (s >= 0.f ? jvd.y * iplo.y : jvd.z * iplo.z) : 0.f;
            s = jvd.x + iphi.x;
            float wd1 = (td & 256u) ? (s >= 0.f ? jvd.y * iphi.y : jvd.z * iphi.z) : 0.f;

            unsigned afr[4];
            afr[0] = pack_h2(wa0, wb0);   // {A[rr][ja] lo, A[rr][ja+1] hi}
            afr[1] = pack_h2(wa1, wb1);   // rows rr+8
            afr[2] = pack_h2(wc0, wd0);
            afr[3] = pack_h2(wc1, wd1);

            const int jjb = kg * 8 + cc;            // half2-word column base
#pragma unroll
            for (int nb = 0; nb < 8; nb++) {
                unsigned bfr[2];
                bfr[0] = Bs[bf][nb * 8 + rr][jjb];
                bfr[1] = Bs[bf][nb * 8 + rr][jjb + 4];
                mma_f16(acc[nb], afr, bfr);
            }
        }

        if (jt + 1 < jt1) STS_TILE(bf ^ 1);
        __syncthreads();
    }

    // epilogue: write raw partials to g_part[spl][kh][i][d]
    float* pbase = part + ((size_t)(spl * KH + kh) * NN) * DD;
    const int ilo = i0 + mi * 16 + rr;
#pragma unroll
    for (int nb = 0; nb < 8; nb++) {
        int col = nb * 8 + 2 * cc;
        *(float2*)(pbase + (size_t)ilo * DD + col) = make_float2(acc[nb][0], acc[nb][1]);
        *(float2*)(pbase + (size_t)(ilo + 8) * DD + col) = make_float2(acc[nb][2], acc[nb][3]);
    }
#undef LDG_TILE
#undef STS_TILE
}

// ------- kernel 5: reduce partials + bias + relu ----------------------------
__global__ void k_fin(const float* __restrict__ bias, float* __restrict__ out) {
    const int t = blockIdx.x * 256 + threadIdx.x;   // float4 id over [NN][K*D]
    const int d4 = t & 31;            // 0..31 (float4 within 128-float row)
    const int i  = t >> 5;
    const int kh = d4 >> 4;           // head
    const int dd4 = d4 & 15;          // float4 within head (d = dd4*4)
    const size_t pidx = (((size_t)kh * NN + i) * DD + dd4 * 4) / 4;

    const float4* P = (const float4*)g_part;
    const size_t stride4 = (size_t)KH * NN * DD / 4;
    float4 s0 = P[pidx];
    float4 s1 = P[pidx + stride4];
    float4 s2 = P[pidx + 2 * stride4];
    float4 s3 = P[pidx + 3 * stride4];
    float4 bv = *(const float4*)(bias + kh * DD + dd4 * 4);
    float4 o;
    o.x = fmaxf((s0.x + s1.x) + (s2.x + s3.x) + bv.x, 0.f);
    o.y = fmaxf((s0.y + s1.y) + (s2.y + s3.y) + bv.y, 0.f);
    o.z = fmaxf((s0.z + s1.z) + (s2.z + s3.z) + bv.z, 0.f);
    o.w = fmaxf((s0.w + s1.w) + (s2.w + s3.w) + bv.w, 0.f);
    ((float4*)out)[t] = o;
}

// ---------------------------------------------------------------------------
extern "C" void kernel_launch(void* const* d_in, const int* in_sizes, int n_in,
                              void* d_out, int out_size) {
    const float* H  = (const float*)d_in[0];   // [8192,256]
    const int*   A  = (const int*)  d_in[1];   // [8192,8192]
    const float* W  = (const float*)d_in[2];   // [2,256,64]
    const float* b  = (const float*)d_in[3];   // [2,64]
    const float* a1 = (const float*)d_in[4];   // [2,64]
    const float* a2 = (const float*)d_in[5];   // [2,64]
    float* out = (float*)d_out;                // [8192,128]

    float* part;
    cudaGetSymbolAddress((void**)&part, g_part);

    k_hw <<<NN / 32, 256>>>(H, W);
    k_e  <<<(KH * NN) / 256, 256>>>(a1, a2);
    k_z  <<<NN / 8, 256>>>(A);
    k_out_mma<<<dim3(NN / 64, KH, JSPLIT), 128>>>(part);
    k_fin<<<(NN * KH * DD / 4) / 256, 256>>>(b, out);
}

// round 11
// speedup vs baseline: 2.3133x; 1.4175x over previous
#include <cuda_runtime.h>
#include <math.h>
#include <cstdint>

#define NN 8192
#define FF 256
#define DD 64
#define KH 2
#define JSPLIT 8

// ---------------- scratch (static device globals; no allocation) -------------
__device__ float g_HW [KH*NN*DD];     // [k][n][d] fp32 (for k_e)
__device__ unsigned g_HWp[KH*(NN/2)*DD]; // [k][j/2][d] half2{HW[2jj][d],HW[2jj+1][d]}
__device__ float g_e1 [KH*NN];
__device__ float g_p1 [KH*NN];        // exp(e1)
__device__ float g_p51[KH*NN];        // exp(0.2 e1)
__device__ float4 g_ip [KH*NN];       // {e2, p2=exp(e2), p52=exp(0.2 e2), 0}
__device__ float4 g_jp [KH*NN];       // {e1, q1=p1/Z, q5=p51/Z, 0}
__device__ unsigned g_mask[NN*(NN/32)];  // bitpacked A, row-major [j][i/32]
__device__ float g_part[JSPLIT*KH*NN*DD]; // partial outputs [s][k][i][d]

// ---------------- small PTX helpers (plain sm_80+ PTX) ----------------------
__device__ __forceinline__ unsigned pack_h2(float lo, float hi) {
    unsigned r;
    asm("cvt.rn.f16x2.f32 %0, %1, %2;" : "=r"(r) : "f"(hi), "f"(lo));
    return r;
}
__device__ __forceinline__ void mma_f16(float* d, const unsigned* a, const unsigned* bf) {
    asm volatile(
        "mma.sync.aligned.m16n8k16.row.col.f32.f16.f16.f32 "
        "{%0,%1,%2,%3}, {%4,%5,%6,%7}, {%8,%9}, {%0,%1,%2,%3};"
        : "+f"(d[0]), "+f"(d[1]), "+f"(d[2]), "+f"(d[3])
        : "r"(a[0]), "r"(a[1]), "r"(a[2]), "r"(a[3]), "r"(bf[0]), "r"(bf[1]));
}

// ---------------- kernel 1: HW[k][n][d] = sum_f H[n][f] W[k][f][d] ----------
// Also writes the half2-packed copy g_HWp used by k_out.
__global__ void k_hw(const float* __restrict__ H, const float* __restrict__ W) {
    __shared__ float Ws[64][128];
    __shared__ float Hs[32][64];
    const int tid = threadIdx.x;
    const int tx = tid & 31;
    const int ty = tid >> 5;
    const int n0 = blockIdx.x * 32;

    float acc[4][4];
#pragma unroll
    for (int a = 0; a < 4; a++)
#pragma unroll
        for (int b = 0; b < 4; b++) acc[a][b] = 0.f;

    for (int fc = 0; fc < FF; fc += 64) {
#pragma unroll
        for (int q = 0; q < 8; q++) {
            int idx = q * 256 + tid;
            int kk = idx >> 5, c4 = idx & 31;
            int c = c4 * 4;
            int k = c >> 6, d = c & 63;
            float4 v = *(const float4*)(W + k * (FF * DD) + (fc + kk) * DD + d);
            *(float4*)(&Ws[kk][c]) = v;
        }
#pragma unroll
        for (int q = 0; q < 2; q++) {
            int idx = q * 256 + tid;
            int r = idx >> 4, k4 = idx & 15;
            float4 v = *(const float4*)(H + (n0 + r) * FF + fc + k4 * 4);
            *(float4*)(&Hs[r][k4 * 4]) = v;
        }
        __syncthreads();
#pragma unroll 8
        for (int kk = 0; kk < 64; kk++) {
            float4 bv = *(const float4*)(&Ws[kk][tx * 4]);
            float a0 = Hs[ty * 4 + 0][kk];
            float a1 = Hs[ty * 4 + 1][kk];
            float a2 = Hs[ty * 4 + 2][kk];
            float a3 = Hs[ty * 4 + 3][kk];
            acc[0][0] += a0 * bv.x; acc[0][1] += a0 * bv.y; acc[0][2] += a0 * bv.z; acc[0][3] += a0 * bv.w;
            acc[1][0] += a1 * bv.x; acc[1][1] += a1 * bv.y; acc[1][2] += a1 * bv.z; acc[1][3] += a1 * bv.w;
            acc[2][0] += a2 * bv.x; acc[2][1] += a2 * bv.y; acc[2][2] += a2 * bv.z; acc[2][3] += a2 * bv.w;
            acc[3][0] += a3 * bv.x; acc[3][1] += a3 * bv.y; acc[3][2] += a3 * bv.z; acc[3][3] += a3 * bv.w;
        }
        __syncthreads();
    }
    const int c = tx * 4;
    const int k = c >> 6, d = c & 63;
#pragma unroll
    for (int s = 0; s < 4; s++) {
        int n = n0 + ty * 4 + s;
        float4 o = make_float4(acc[s][0], acc[s][1], acc[s][2], acc[s][3]);
        *(float4*)(g_HW + (k * NN + n) * DD + d) = o;
    }
    // packed half2 copy: rows (2jj, 2jj+1)
    {
        const int jj0 = ((n0 + ty * 4) >> 1);     // rows ty*4+0/1 -> jj0, +2/3 -> jj0+1
        uint4 w0, w1;
        w0.x = pack_h2(acc[0][0], acc[1][0]);
        w0.y = pack_h2(acc[0][1], acc[1][1]);
        w0.z = pack_h2(acc[0][2], acc[1][2]);
        w0.w = pack_h2(acc[0][3], acc[1][3]);
        w1.x = pack_h2(acc[2][0], acc[3][0]);
        w1.y = pack_h2(acc[2][1], acc[3][1]);
        w1.z = pack_h2(acc[2][2], acc[3][2]);
        w1.w = pack_h2(acc[2][3], acc[3][3]);
        *(uint4*)(g_HWp + ((size_t)(k * (NN / 2) + jj0) * DD + d))     = w0;
        *(uint4*)(g_HWp + ((size_t)(k * (NN / 2) + jj0 + 1) * DD + d)) = w1;
    }
}

// ------- kernel 2: e1/e2 per (k,n) + exp tables (packed) --------------------
__global__ void k_e(const float* __restrict__ a1, const float* __restrict__ a2) {
    __shared__ float a1s[128], a2s[128];
    const int tid = threadIdx.x;
    if (tid < 128) a1s[tid] = a1[tid];
    else           a2s[tid - 128] = a2[tid - 128];
    __syncthreads();
    const int t = blockIdx.x * 256 + tid;     // t = k*8192 + n
    const int k = t >> 13;
    const float* hw = g_HW + (size_t)t * DD;
    const float* A1 = a1s + k * 64;
    const float* A2 = a2s + k * 64;
    float e1 = 0.f, e2 = 0.f;
#pragma unroll
    for (int d4 = 0; d4 < 16; d4++) {
        float4 h = *(const float4*)(hw + d4 * 4);
        e1 += h.x * A1[d4 * 4 + 0] + h.y * A1[d4 * 4 + 1] + h.z * A1[d4 * 4 + 2] + h.w * A1[d4 * 4 + 3];
        e2 += h.x * A2[d4 * 4 + 0] + h.y * A2[d4 * 4 + 1] + h.z * A2[d4 * 4 + 2] + h.w * A2[d4 * 4 + 3];
    }
    g_e1[t]  = e1;
    g_p1[t]  = expf(e1);
    g_p51[t] = expf(0.2f * e1);
    g_ip[t]  = make_float4(e2, expf(e2), expf(0.2f * e2), 0.f);
}

// ------- kernel 3: softmax denominators Z + bitpack A (branchless) ----------
__global__ void k_z(const int* __restrict__ A) {
    __shared__ float red[32][8];
    const int tid = threadIdx.x;
    const int lane = tid & 31, wrp = tid >> 5;
    const int j0 = blockIdx.x * 8;

    float e1r[8][2];
#pragma unroll
    for (int j = 0; j < 8; j++) {
        e1r[j][0] = g_e1[j0 + j];
        e1r[j][1] = g_e1[NN + j0 + j];
    }
    float sums[8][2][2];
#pragma unroll
    for (int j = 0; j < 8; j++)
#pragma unroll
        for (int k = 0; k < 2; k++) { sums[j][k][0] = 0.f; sums[j][k][1] = 0.f; }

    for (int ci = 0; ci < 32; ci++) {
        const int col = ci * 256 + tid;
        const float4 ip0 = g_ip[col];
        const float4 ip1 = g_ip[NN + col];
#pragma unroll
        for (int j = 0; j < 8; j++) {
            int a = A[(size_t)(j0 + j) * NN + col];
            unsigned bal = __ballot_sync(0xffffffffu, a != 0);
            if (lane == 0) g_mask[(j0 + j) * (NN / 32) + ci * 8 + wrp] = bal;
            float am = (a != 0) ? 1.0f : 0.0f;
            {
                float s = e1r[j][0] + ip0.x;
                bool pos = s >= 0.f;
                sums[j][0][0] += am * (pos ? ip0.y : 0.f);
                sums[j][0][1] += am * (pos ? 0.f : ip0.z);
            }
            {
                float s = e1r[j][1] + ip1.x;
                bool pos = s >= 0.f;
                sums[j][1][0] += am * (pos ? ip1.y : 0.f);
                sums[j][1][1] += am * (pos ? 0.f : ip1.z);
            }
        }
    }
#pragma unroll
    for (int v = 0; v < 32; v++) {
        int j = v >> 2, k = (v >> 1) & 1, tp = v & 1;
        float val = sums[j][k][tp];
        val += __shfl_down_sync(0xffffffffu, val, 16);
        val += __shfl_down_sync(0xffffffffu, val, 8);
        val += __shfl_down_sync(0xffffffffu, val, 4);
        val += __shfl_down_sync(0xffffffffu, val, 2);
        val += __shfl_down_sync(0xffffffffu, val, 1);
        if (lane == 0) red[v][wrp] = val;
    }
    __syncthreads();
    if (tid < 16) {
        int j = tid >> 1, k = tid & 1;
        float s0 = 0.f, s5 = 0.f;
#pragma unroll
        for (int w = 0; w < 8; w++) {
            s0 += red[(j * 2 + k) * 2 + 0][w];
            s5 += red[(j * 2 + k) * 2 + 1][w];
        }
        int gi = k * NN + j0 + j;
        float p1 = g_p1[gi], p51 = g_p51[gi];
        float rZ = 1.0f / (p1 * s0 + p51 * s5);
        g_jp[gi] = make_float4(g_e1[gi], p1 * rZ, p51 * rZ, 0.f);
    }
}

// ------- kernel 4 (f16 mma, i-tile 128 / 8 warps m16n64, pre-packed B) ------
// CTA (bx, kh, s): i-tile bx*128, head kh, j-range split s (1024 j each).
// B staged straight from g_HWp (half2 packed): 1 LDG.128 + 1 STS.128/thread.
// Bs layout [jj][d] stride 72 -> frag reads conflict-free.
__global__ void __launch_bounds__(256) k_out_mma(float* __restrict__ part) {
    __shared__ unsigned Bs[2][16][72];      // half2{2jj,2jj+1}, [jj][d]
    __shared__ float4   jtab[2][32];        // {e1, q1, q5, -}
    __shared__ unsigned maskt[2][32][4];    // [j][word]

    const int tid  = threadIdx.x;
    const int lane = tid & 31;
    const int wid  = tid >> 5;
    const int kh   = blockIdx.y;
    const int spl  = blockIdx.z;
    const int i0   = blockIdx.x * 128;
    const int kbase = kh * NN;
    const int kb2   = kh * (NN / 2);
    const int mrow0 = i0 >> 5;
    const int jt0  = spl * (NN / 32 / JSPLIT);     // 32 tiles per split
    const int jt1  = jt0 + (NN / 32 / JSPLIT);

    const int mi = wid;                 // m16 block 0..7
    const int rr = lane >> 2;           // 0..7
    const int cc = lane & 3;            // 0..3
    const int wsel = mi >> 1;           // mask word within 128-i tile
    const int bplo = (mi & 1) * 16 + rr;

    const float4 iplo = g_ip[kbase + i0 + mi * 16 + rr];
    const float4 iphi = g_ip[kbase + i0 + mi * 16 + rr + 8];

    // B-stage coords: thread t stages uint4 at (jj = t>>4, d0 = (t&15)*4)
    const int bjj = tid >> 4;
    const int bd0 = (tid & 15) * 4;

    const int mjj = (tid - 32) >> 2;    // valid for tid in [32,160): 0..31
    const int mword = (tid - 32) & 3;

    uint4 rBu;
    float4 rJ;
    unsigned rM = 0;

#define LDG_TILE(JT) do {                                                        \
    const int jj0_ = (JT) * 16;                                                  \
    rBu = *(const uint4*)(g_HWp + ((size_t)(kb2 + jj0_ + bjj) * DD + bd0));      \
    if (tid < 32)       rJ = g_jp[kbase + (JT) * 32 + tid];                      \
    else if (tid < 160) rM = g_mask[((JT) * 32 + mjj) * (NN / 32) + mrow0 + mword]; \
} while (0)

#define STS_TILE(BUF) do {                                                       \
    *(uint4*)(&Bs[BUF][bjj][bd0]) = rBu;                                         \
    if (tid < 32)       jtab[BUF][tid] = rJ;                                     \
    else if (tid < 160) maskt[BUF][mjj][mword] = rM;                             \
} while (0)

    float acc[8][4];
#pragma unroll
    for (int nb = 0; nb < 8; nb++)
#pragma unroll
        for (int q = 0; q < 4; q++) acc[nb][q] = 0.f;

    LDG_TILE(jt0);
    STS_TILE(0);
    __syncthreads();

    for (int jt = jt0; jt < jt1; jt++) {
        const int bf = (jt - jt0) & 1;
        if (jt + 1 < jt1) LDG_TILE(jt + 1);

#pragma unroll
        for (int kg = 0; kg < 2; kg++) {            // two k16 groups per 32-j tile
            const int jb = kg * 16;
            const int ja = jb + 2 * cc;             // even j
            const int jc = jb + 2 * cc + 8;
            const float4 jva = jtab[bf][ja];
            const float4 jvb = jtab[bf][ja + 1];
            const float4 jvc = jtab[bf][jc];
            const float4 jvd = jtab[bf][jc + 1];
            const unsigned ta = maskt[bf][ja][wsel]     >> bplo;
            const unsigned tb = maskt[bf][ja + 1][wsel] >> bplo;
            const unsigned tc = maskt[bf][jc][wsel]     >> bplo;
            const unsigned td = maskt[bf][jc + 1][wsel] >> bplo;

            float s;
            s = jva.x + iplo.x;
            float wa0 = (ta & 1u)   ? (s >= 0.f ? jva.y * iplo.y : jva.z * iplo.z) : 0.f;
            s = jva.x + iphi.x;
            float wa1 = (ta & 256u) ? (s >= 0.f ? jva.y * iphi.y : jva.z * iphi.z) : 0.f;
            s = jvb.x + iplo.x;
            float wb0 = (tb & 1u)   ? (s >= 0.f ? jvb.y * iplo.y : jvb.z * iplo.z) : 0.f;
            s = jvb.x + iphi.x;
            float wb1 = (tb & 256u) ? (s >= 0.f ? jvb.y * iphi.y : jvb.z * iphi.z) : 0.f;
            s = jvc.x + iplo.x;
            float wc0 = (tc & 1u)   ? (s >= 0.f ? jvc.y * iplo.y : jvc.z * iplo.z) : 0.f;
            s = jvc.x + iphi.x;
            float wc1 = (tc & 256u) ? (s >= 0.f ? jvc.y * iphi.y : jvc.z * iphi.z) : 0.f;
            s = jvd.x + iplo.x;
            float wd0 = (td & 1u)   ? (s >= 0.f ? jvd.y * iplo.y : jvd.z * iplo.z) : 0.f;
            s = jvd.x + iphi.x;
            float wd1 = (td & 256u) ? (s >= 0.f ? jvd.y * iphi.y : jvd.z * iphi.z) : 0.f;

            unsigned afr[4];
            afr[0] = pack_h2(wa0, wb0);
            afr[1] = pack_h2(wa1, wb1);
            afr[2] = pack_h2(wc0, wd0);
            afr[3] = pack_h2(wc1, wd1);

            const int jjb = kg * 8 + cc;            // half2 column base
#pragma unroll
            for (int nb = 0; nb < 8; nb++) {
                unsigned bfr[2];
                bfr[0] = Bs[bf][jjb][nb * 8 + rr];
                bfr[1] = Bs[bf][jjb + 4][nb * 8 + rr];
                mma_f16(acc[nb], afr, bfr);
            }
        }

        if (jt + 1 < jt1) STS_TILE(bf ^ 1);
        __syncthreads();
    }

    // epilogue: write raw partials to g_part[spl][kh][i][d]
    float* pbase = part + ((size_t)(spl * KH + kh) * NN) * DD;
    const int ilo = i0 + mi * 16 + rr;
#pragma unroll
    for (int nb = 0; nb < 8; nb++) {
        int col = nb * 8 + 2 * cc;
        *(float2*)(pbase + (size_t)ilo * DD + col) = make_float2(acc[nb][0], acc[nb][1]);
        *(float2*)(pbase + (size_t)(ilo + 8) * DD + col) = make_float2(acc[nb][2], acc[nb][3]);
    }
#undef LDG_TILE
#undef STS_TILE
}

// ------- kernel 5: reduce partials + bias + relu ----------------------------
__global__ void k_fin(const float* __restrict__ bias, float* __restrict__ out) {
    const int t = blockIdx.x * 256 + threadIdx.x;   // float4 id over [NN][K*D]
    const int d4 = t & 31;            // float4 within 128-float row
    const int i  = t >> 5;
    const int kh = d4 >> 4;           // head
    const int dd4 = d4 & 15;          // float4 within head
    const size_t pidx = (((size_t)kh * NN + i) * DD + dd4 * 4) / 4;

    const float4* P = (const float4*)g_part;
    const size_t stride4 = (size_t)KH * NN * DD / 4;
    float4 acc = P[pidx];
#pragma unroll
    for (int s = 1; s < JSPLIT; s++) {
        float4 v = P[pidx + (size_t)s * stride4];
        acc.x += v.x; acc.y += v.y; acc.z += v.z; acc.w += v.w;
    }
    float4 bv = *(const float4*)(bias + kh * DD + dd4 * 4);
    float4 o;
    o.x = fmaxf(acc.x + bv.x, 0.f);
    o.y = fmaxf(acc.y + bv.y, 0.f);
    o.z = fmaxf(acc.z + bv.z, 0.f);
    o.w = fmaxf(acc.w + bv.w, 0.f);
    ((float4*)out)[t] = o;
}

// ---------------------------------------------------------------------------
extern "C" void kernel_launch(void* const* d_in, const int* in_sizes, int n_in,
                              void* d_out, int out_size) {
    const float* H  = (const float*)d_in[0];   // [8192,256]
    const int*   A  = (const int*)  d_in[1];   // [8192,8192]
    const float* W  = (const float*)d_in[2];   // [2,256,64]
    const float* b  = (const float*)d_in[3];   // [2,64]
    const float* a1 = (const float*)d_in[4];   // [2,64]
    const float* a2 = (const float*)d_in[5];   // [2,64]
    float* out = (float*)d_out;                // [8192,128]

    float* part;
    cudaGetSymbolAddress((void**)&part, g_part);

    k_hw <<<NN / 32, 256>>>(H, W);
    k_e  <<<(KH * NN) / 256, 256>>>(a1, a2);
    k_z  <<<NN / 8, 256>>>(A);
    k_out_mma<<<dim3(NN / 128, KH, JSPLIT), 256>>>(part);
    k_fin<<<(NN * KH * DD / 4) / 256, 256>>>(b, out);
}

// round 12
// speedup vs baseline: 3.1173x; 1.3475x over previous
#include <cuda_runtime.h>
#include <math.h>
#include <cstdint>

#define NN 8192
#define FF 256
#define DD 64
#define KH 2
#define JSPLIT 8

// ---------------- scratch (static device globals; no allocation) -------------
__device__ float g_HW [KH*NN*DD];        // [k][n][d] fp32 (for k_e)
__device__ unsigned g_HWp[KH*(NN/2)*DD]; // [k][j/2][d] half2{HW[2jj][d],HW[2jj+1][d]}
__device__ float  g_rho[KH*NN];          // exp(-0.8*e1) = p51/p1
__device__ float2 g_ip2[KH*NN];          // {p2=exp(e2), p52=exp(0.2*e2)}
__device__ float2 g_jp2[KH*NN];          // {q1=p1/Z, q5=p51/Z}
__device__ unsigned g_mask[NN*(NN/32)];  // bitpacked A, row-major [j][i/32]
__device__ float g_part[JSPLIT*KH*NN*DD]; // partial outputs [s][k][i][d]

// ---------------- small PTX helpers (plain sm_80+ PTX) ----------------------
__device__ __forceinline__ unsigned pack_h2(float lo, float hi) {
    unsigned r;
    asm("cvt.rn.f16x2.f32 %0, %1, %2;" : "=r"(r) : "f"(hi), "f"(lo));
    return r;
}
__device__ __forceinline__ void mma_f16(float* d, const unsigned* a, const unsigned* bf) {
    asm volatile(
        "mma.sync.aligned.m16n8k16.row.col.f32.f16.f16.f32 "
        "{%0,%1,%2,%3}, {%4,%5,%6,%7}, {%8,%9}, {%0,%1,%2,%3};"
        : "+f"(d[0]), "+f"(d[1]), "+f"(d[2]), "+f"(d[3])
        : "r"(a[0]), "r"(a[1]), "r"(a[2]), "r"(a[3]), "r"(bf[0]), "r"(bf[1]));
}

// ---------------- kernel 1: HW[k][n][d] = sum_f H[n][f] W[k][f][d] ----------
// Also writes the half2-packed copy g_HWp used by k_out.
__global__ void k_hw(const float* __restrict__ H, const float* __restrict__ W) {
    __shared__ float Ws[64][128];
    __shared__ float Hs[32][64];
    const int tid = threadIdx.x;
    const int tx = tid & 31;
    const int ty = tid >> 5;
    const int n0 = blockIdx.x * 32;

    float acc[4][4];
#pragma unroll
    for (int a = 0; a < 4; a++)
#pragma unroll
        for (int b = 0; b < 4; b++) acc[a][b] = 0.f;

    for (int fc = 0; fc < FF; fc += 64) {
#pragma unroll
        for (int q = 0; q < 8; q++) {
            int idx = q * 256 + tid;
            int kk = idx >> 5, c4 = idx & 31;
            int c = c4 * 4;
            int k = c >> 6, d = c & 63;
            float4 v = *(const float4*)(W + k * (FF * DD) + (fc + kk) * DD + d);
            *(float4*)(&Ws[kk][c]) = v;
        }
#pragma unroll
        for (int q = 0; q < 2; q++) {
            int idx = q * 256 + tid;
            int r = idx >> 4, k4 = idx & 15;
            float4 v = *(const float4*)(H + (n0 + r) * FF + fc + k4 * 4);
            *(float4*)(&Hs[r][k4 * 4]) = v;
        }
        __syncthreads();
#pragma unroll 8
        for (int kk = 0; kk < 64; kk++) {
            float4 bv = *(const float4*)(&Ws[kk][tx * 4]);
            float a0 = Hs[ty * 4 + 0][kk];
            float a1 = Hs[ty * 4 + 1][kk];
            float a2 = Hs[ty * 4 + 2][kk];
            float a3 = Hs[ty * 4 + 3][kk];
            acc[0][0] += a0 * bv.x; acc[0][1] += a0 * bv.y; acc[0][2] += a0 * bv.z; acc[0][3] += a0 * bv.w;
            acc[1][0] += a1 * bv.x; acc[1][1] += a1 * bv.y; acc[1][2] += a1 * bv.z; acc[1][3] += a1 * bv.w;
            acc[2][0] += a2 * bv.x; acc[2][1] += a2 * bv.y; acc[2][2] += a2 * bv.z; acc[2][3] += a2 * bv.w;
            acc[3][0] += a3 * bv.x; acc[3][1] += a3 * bv.y; acc[3][2] += a3 * bv.z; acc[3][3] += a3 * bv.w;
        }
        __syncthreads();
    }
    const int c = tx * 4;
    const int k = c >> 6, d = c & 63;
#pragma unroll
    for (int s = 0; s < 4; s++) {
        int n = n0 + ty * 4 + s;
        float4 o = make_float4(acc[s][0], acc[s][1], acc[s][2], acc[s][3]);
        *(float4*)(g_HW + (k * NN + n) * DD + d) = o;
    }
    // packed half2 copy: rows (2jj, 2jj+1)
    {
        const int jj0 = ((n0 + ty * 4) >> 1);
        uint4 w0, w1;
        w0.x = pack_h2(acc[0][0], acc[1][0]);
        w0.y = pack_h2(acc[0][1], acc[1][1]);
        w0.z = pack_h2(acc[0][2], acc[1][2]);
        w0.w = pack_h2(acc[0][3], acc[1][3]);
        w1.x = pack_h2(acc[2][0], acc[3][0]);
        w1.y = pack_h2(acc[2][1], acc[3][1]);
        w1.z = pack_h2(acc[2][2], acc[3][2]);
        w1.w = pack_h2(acc[2][3], acc[3][3]);
        *(uint4*)(g_HWp + ((size_t)(k * (NN / 2) + jj0) * DD + d))     = w0;
        *(uint4*)(g_HWp + ((size_t)(k * (NN / 2) + jj0 + 1) * DD + d)) = w1;
    }
}

// ------- kernel 2: e1/e2 per (k,n) -> rho + {p2,p52} tables -----------------
__global__ void k_e(const float* __restrict__ a1, const float* __restrict__ a2) {
    __shared__ float a1s[128], a2s[128];
    const int tid = threadIdx.x;
    if (tid < 128) a1s[tid] = a1[tid];
    else           a2s[tid - 128] = a2[tid - 128];
    __syncthreads();
    const int t = blockIdx.x * 256 + tid;     // t = k*8192 + n
    const int k = t >> 13;
    const float* hw = g_HW + (size_t)t * DD;
    const float* A1 = a1s + k * 64;
    const float* A2 = a2s + k * 64;
    float e1 = 0.f, e2 = 0.f;
#pragma unroll
    for (int d4 = 0; d4 < 16; d4++) {
        float4 h = *(const float4*)(hw + d4 * 4);
        e1 += h.x * A1[d4 * 4 + 0] + h.y * A1[d4 * 4 + 1] + h.z * A1[d4 * 4 + 2] + h.w * A1[d4 * 4 + 3];
        e2 += h.x * A2[d4 * 4 + 0] + h.y * A2[d4 * 4 + 1] + h.z * A2[d4 * 4 + 2] + h.w * A2[d4 * 4 + 3];
    }
    g_rho[t] = expf(-0.8f * e1);             // p51/p1
    g_ip2[t] = make_float2(expf(e2), expf(0.2f * e2));
}

// ------- kernel 3: softmax denominators + bitpack A (max-trick) -------------
// Z[j] = p1 * sum_i am * max(p2_i, rho_j * p52_i); q1 = 1/Zacc, q5 = rho*q1.
__global__ void k_z(const int* __restrict__ A) {
    __shared__ float red[16][8];
    const int tid = threadIdx.x;
    const int lane = tid & 31, wrp = tid >> 5;
    const int j0 = blockIdx.x * 8;

    float rho[8][2];
#pragma unroll
    for (int j = 0; j < 8; j++) {
        rho[j][0] = g_rho[j0 + j];
        rho[j][1] = g_rho[NN + j0 + j];
    }
    float z[8][2];
#pragma unroll
    for (int j = 0; j < 8; j++) { z[j][0] = 0.f; z[j][1] = 0.f; }

    for (int ci = 0; ci < 32; ci++) {
        const int col = ci * 256 + tid;
        const float2 ip0 = g_ip2[col];
        const float2 ip1 = g_ip2[NN + col];
#pragma unroll
        for (int j = 0; j < 8; j++) {
            int a = A[(size_t)(j0 + j) * NN + col];
            unsigned bal = __ballot_sync(0xffffffffu, a != 0);
            if (lane == 0) g_mask[(j0 + j) * (NN / 32) + ci * 8 + wrp] = bal;
            float am = (a != 0) ? 1.0f : 0.0f;
            z[j][0] += am * fmaxf(ip0.x, rho[j][0] * ip0.y);
            z[j][1] += am * fmaxf(ip1.x, rho[j][1] * ip1.y);
        }
    }
#pragma unroll
    for (int v = 0; v < 16; v++) {
        int j = v >> 1, k = v & 1;
        float val = z[j][k];
        val += __shfl_down_sync(0xffffffffu, val, 16);
        val += __shfl_down_sync(0xffffffffu, val, 8);
        val += __shfl_down_sync(0xffffffffu, val, 4);
        val += __shfl_down_sync(0xffffffffu, val, 2);
        val += __shfl_down_sync(0xffffffffu, val, 1);
        if (lane == 0) red[v][wrp] = val;
    }
    __syncthreads();
    if (tid < 16) {
        int j = tid >> 1, k = tid & 1;
        float s = 0.f;
#pragma unroll
        for (int w = 0; w < 8; w++) s += red[tid][w];
        int gi = k * NN + j0 + j;
        float q1 = 1.0f / s;
        float q5 = g_rho[gi] * q1;
        g_jp2[gi] = make_float2(q1, q5);
    }
}

// ------- kernel 4 (f16 mma, i-tile 128 / 8 warps m16n64, pre-packed B) ------
// Weight build via the max identity: w = edge ? max(q1*p2, q5*p52) : 0.
__global__ void __launch_bounds__(256) k_out_mma(float* __restrict__ part) {
    __shared__ unsigned Bs[2][16][72];      // half2{2jj,2jj+1}, [jj][d]
    __shared__ float2   jtab[2][32];        // {q1, q5}
    __shared__ unsigned maskt[2][32][4];    // [j][word]

    const int tid  = threadIdx.x;
    const int lane = tid & 31;
    const int wid  = tid >> 5;
    const int kh   = blockIdx.y;
    const int spl  = blockIdx.z;
    const int i0   = blockIdx.x * 128;
    const int kbase = kh * NN;
    const int kb2   = kh * (NN / 2);
    const int mrow0 = i0 >> 5;
    const int jt0  = spl * (NN / 32 / JSPLIT);     // 32 tiles per split
    const int jt1  = jt0 + (NN / 32 / JSPLIT);

    const int mi = wid;                 // m16 block 0..7
    const int rr = lane >> 2;           // 0..7
    const int cc = lane & 3;            // 0..3
    const int wsel = mi >> 1;           // mask word within 128-i tile
    const int bplo = (mi & 1) * 16 + rr;

    const float2 iplo = g_ip2[kbase + i0 + mi * 16 + rr];      // {p2, p52}
    const float2 iphi = g_ip2[kbase + i0 + mi * 16 + rr + 8];

    // B-stage coords: thread t stages uint4 at (jj = t>>4, d0 = (t&15)*4)
    const int bjj = tid >> 4;
    const int bd0 = (tid & 15) * 4;

    const int mjj = (tid - 32) >> 2;    // valid for tid in [32,160): 0..31
    const int mword = (tid - 32) & 3;

    uint4 rBu;
    float2 rJ;
    unsigned rM = 0;

#define LDG_TILE(JT) do {                                                        \
    const int jj0_ = (JT) * 16;                                                  \
    rBu = *(const uint4*)(g_HWp + ((size_t)(kb2 + jj0_ + bjj) * DD + bd0));      \
    if (tid < 32)       rJ = g_jp2[kbase + (JT) * 32 + tid];                     \
    else if (tid < 160) rM = g_mask[((JT) * 32 + mjj) * (NN / 32) + mrow0 + mword]; \
} while (0)

#define STS_TILE(BUF) do {                                                       \
    *(uint4*)(&Bs[BUF][bjj][bd0]) = rBu;                                         \
    if (tid < 32)       jtab[BUF][tid] = rJ;                                     \
    else if (tid < 160) maskt[BUF][mjj][mword] = rM;                             \
} while (0)

    float acc[8][4];
#pragma unroll
    for (int nb = 0; nb < 8; nb++)
#pragma unroll
        for (int q = 0; q < 4; q++) acc[nb][q] = 0.f;

    LDG_TILE(jt0);
    STS_TILE(0);
    __syncthreads();

    for (int jt = jt0; jt < jt1; jt++) {
        const int bf = (jt - jt0) & 1;
        if (jt + 1 < jt1) LDG_TILE(jt + 1);

#pragma unroll
        for (int kg = 0; kg < 2; kg++) {            // two k16 groups per 32-j tile
            const int jb = kg * 16;
            const int ja = jb + 2 * cc;             // even j
            const int jc = jb + 2 * cc + 8;
            // paired j tables: {q1a,q5a,q1b,q5b}
            const float4 jab = *(const float4*)(&jtab[bf][ja]);
            const float4 jcd = *(const float4*)(&jtab[bf][jc]);
            const unsigned ta = maskt[bf][ja][wsel]     >> bplo;
            const unsigned tb = maskt[bf][ja + 1][wsel] >> bplo;
            const unsigned tc = maskt[bf][jc][wsel]     >> bplo;
            const unsigned td = maskt[bf][jc + 1][wsel] >> bplo;

            float wa0 = (ta & 1u)   ? fmaxf(jab.x * iplo.x, jab.y * iplo.y) : 0.f;
            float wa1 = (ta & 256u) ? fmaxf(jab.x * iphi.x, jab.y * iphi.y) : 0.f;
            float wb0 = (tb & 1u)   ? fmaxf(jab.z * iplo.x, jab.w * iplo.y) : 0.f;
            float wb1 = (tb & 256u) ? fmaxf(jab.z * iphi.x, jab.w * iphi.y) : 0.f;
            float wc0 = (tc & 1u)   ? fmaxf(jcd.x * iplo.x, jcd.y * iplo.y) : 0.f;
            float wc1 = (tc & 256u) ? fmaxf(jcd.x * iphi.x, jcd.y * iphi.y) : 0.f;
            float wd0 = (td & 1u)   ? fmaxf(jcd.z * iplo.x, jcd.w * iplo.y) : 0.f;
            float wd1 = (td & 256u) ? fmaxf(jcd.z * iphi.x, jcd.w * iphi.y) : 0.f;

            unsigned afr[4];
            afr[0] = pack_h2(wa0, wb0);
            afr[1] = pack_h2(wa1, wb1);
            afr[2] = pack_h2(wc0, wd0);
            afr[3] = pack_h2(wc1, wd1);

            const int jjb = kg * 8 + cc;            // half2 column base
#pragma unroll
            for (int nb = 0; nb < 8; nb++) {
                unsigned bfr[2];
                bfr[0] = Bs[bf][jjb][nb * 8 + rr];
                bfr[1] = Bs[bf][jjb + 4][nb * 8 + rr];
                mma_f16(acc[nb], afr, bfr);
            }
        }

        if (jt + 1 < jt1) STS_TILE(bf ^ 1);
        __syncthreads();
    }

    // epilogue: write raw partials to g_part[spl][kh][i][d]
    float* pbase = part + ((size_t)(spl * KH + kh) * NN) * DD;
    const int ilo = i0 + mi * 16 + rr;
#pragma unroll
    for (int nb = 0; nb < 8; nb++) {
        int col = nb * 8 + 2 * cc;
        *(float2*)(pbase + (size_t)ilo * DD + col) = make_float2(acc[nb][0], acc[nb][1]);
        *(float2*)(pbase + (size_t)(ilo + 8) * DD + col) = make_float2(acc[nb][2], acc[nb][3]);
    }
#undef LDG_TILE
#undef STS_TILE
}

// ------- kernel 5: reduce partials + bias + relu ----------------------------
__global__ void k_fin(const float* __restrict__ bias, float* __restrict__ out) {
    const int t = blockIdx.x * 256 + threadIdx.x;   // float4 id over [NN][K*D]
    const int d4 = t & 31;            // float4 within 128-float row
    const int i  = t >> 5;
    const int kh = d4 >> 4;           // head
    const int dd4 = d4 & 15;          // float4 within head
    const size_t pidx = (((size_t)kh * NN + i) * DD + dd4 * 4) / 4;

    const float4* P = (const float4*)g_part;
    const size_t stride4 = (size_t)KH * NN * DD / 4;
    float4 acc = P[pidx];
#pragma unroll
    for (int s = 1; s < JSPLIT; s++) {
        float4 v = P[pidx + (size_t)s * stride4];
        acc.x += v.x; acc.y += v.y; acc.z += v.z; acc.w += v.w;
    }
    float4 bv = *(const float4*)(bias + kh * DD + dd4 * 4);
    float4 o;
    o.x = fmaxf(acc.x + bv.x, 0.f);
    o.y = fmaxf(acc.y + bv.y, 0.f);
    o.z = fmaxf(acc.z + bv.z, 0.f);
    o.w = fmaxf(acc.w + bv.w, 0.f);
    ((float4*)out)[t] = o;
}

// ---------------------------------------------------------------------------
extern "C" void kernel_launch(void* const* d_in, const int* in_sizes, int n_in,
                              void* d_out, int out_size) {
    const float* H  = (const float*)d_in[0];   // [8192,256]
    const int*   A  = (const int*)  d_in[1];   // [8192,8192]
    const float* W  = (const float*)d_in[2];   // [2,256,64]
    const float* b  = (const float*)d_in[3];   // [2,64]
    const float* a1 = (const float*)d_in[4];   // [2,64]
    const float* a2 = (const float*)d_in[5];   // [2,64]
    float* out = (float*)d_out;                // [8192,128]

    float* part;
    cudaGetSymbolAddress((void**)&part, g_part);

    k_hw <<<NN / 32, 256>>>(H, W);
    k_e  <<<(KH * NN) / 256, 256>>>(a1, a2);
    k_z  <<<NN / 8, 256>>>(A);
    k_out_mma<<<dim3(NN / 128, KH, JSPLIT), 256>>>(part);
    k_fin<<<(NN * KH * DD / 4) / 256, 256>>>(b, out);
}

// round 15
// speedup vs baseline: 3.2952x; 1.0570x over previous
#include <cuda_runtime.h>
#include <math.h>
#include <cstdint>

#define NN 8192
#define FF 256
#define DD 64
#define KH 2
#define JSPLIT 8

// ---------------- scratch (static device globals; no allocation) -------------
__device__ float g_HW [KH*NN*DD];        // [k][n][d] fp32 (for k_e)
__device__ unsigned g_HWp[KH*(NN/2)*DD]; // [k][j/2][d] half2{HW[2jj][d],HW[2jj+1][d]}
__device__ float  g_rho[KH*NN];          // exp(-0.8*e1) = p51/p1
__device__ float2 g_ip2[KH*NN];          // {p2=exp(e2), p52=exp(0.2*e2)}
__device__ uint2  g_jph[KH*(NN/2)];      // {half2{q1 even,q1 odd}, half2{q5 even,q5 odd}}
__device__ unsigned g_mask[NN*(NN/32)];  // bitpacked A, row-major [j][i/32]
__device__ float g_part[JSPLIT*KH*NN*DD]; // partial outputs [s][k][i][d]

// ---------------- small PTX helpers (plain sm_80+ PTX) ----------------------
__device__ __forceinline__ unsigned pack_h2(float lo, float hi) {
    unsigned r;
    asm("cvt.rn.f16x2.f32 %0, %1, %2;" : "=r"(r) : "f"(hi), "f"(lo));
    return r;
}
__device__ __forceinline__ unsigned hmul2(unsigned a, unsigned b) {
    unsigned r;
    asm("mul.rn.f16x2 %0, %1, %2;" : "=r"(r) : "r"(a), "r"(b));
    return r;
}
__device__ __forceinline__ unsigned hmax2(unsigned a, unsigned b) {
    unsigned r;
    asm("max.f16x2 %0, %1, %2;" : "=r"(r) : "r"(a), "r"(b));
    return r;
}
// PRMT with sign-replicate nibbles (bit3). __byte_perm's contract only covers
// 3-bit selectors (s<0:2> per the Math API), so replicate mode MUST go through
// inline asm to get the documented PTX prmt hardware semantics.
__device__ __forceinline__ unsigned prmt_repl(unsigned a, unsigned sel) {
    unsigned r;
    asm("prmt.b32 %0, %1, %2, %3;" : "=r"(r) : "r"(a), "n"(0), "r"(sel));
    return r;
}
__device__ __forceinline__ void mma_f16(float* d, const unsigned* a, const unsigned* bf) {
    asm volatile(
        "mma.sync.aligned.m16n8k16.row.col.f32.f16.f16.f32 "
        "{%0,%1,%2,%3}, {%4,%5,%6,%7}, {%8,%9}, {%0,%1,%2,%3};"
        : "+f"(d[0]), "+f"(d[1]), "+f"(d[2]), "+f"(d[3])
        : "r"(a[0]), "r"(a[1]), "r"(a[2]), "r"(a[3]), "r"(bf[0]), "r"(bf[1]));
}

// ---------------- kernel 1: HW[k][n][d] = sum_f H[n][f] W[k][f][d] ----------
// Also writes the half2-packed copy g_HWp used by k_out.
__global__ void k_hw(const float* __restrict__ H, const float* __restrict__ W) {
    __shared__ float Ws[64][128];
    __shared__ float Hs[32][64];
    const int tid = threadIdx.x;
    const int tx = tid & 31;
    const int ty = tid >> 5;
    const int n0 = blockIdx.x * 32;

    float acc[4][4];
#pragma unroll
    for (int a = 0; a < 4; a++)
#pragma unroll
        for (int b = 0; b < 4; b++) acc[a][b] = 0.f;

    for (int fc = 0; fc < FF; fc += 64) {
#pragma unroll
        for (int q = 0; q < 8; q++) {
            int idx = q * 256 + tid;
            int kk = idx >> 5, c4 = idx & 31;
            int c = c4 * 4;
            int k = c >> 6, d = c & 63;
            float4 v = *(const float4*)(W + k * (FF * DD) + (fc + kk) * DD + d);
            *(float4*)(&Ws[kk][c]) = v;
        }
#pragma unroll
        for (int q = 0; q < 2; q++) {
            int idx = q * 256 + tid;
            int r = idx >> 4, k4 = idx & 15;
            float4 v = *(const float4*)(H + (n0 + r) * FF + fc + k4 * 4);
            *(float4*)(&Hs[r][k4 * 4]) = v;
        }
        __syncthreads();
#pragma unroll 8
        for (int kk = 0; kk < 64; kk++) {
            float4 bv = *(const float4*)(&Ws[kk][tx * 4]);
            float a0 = Hs[ty * 4 + 0][kk];
            float a1 = Hs[ty * 4 + 1][kk];
            float a2 = Hs[ty * 4 + 2][kk];
            float a3 = Hs[ty * 4 + 3][kk];
            acc[0][0] += a0 * bv.x; acc[0][1] += a0 * bv.y; acc[0][2] += a0 * bv.z; acc[0][3] += a0 * bv.w;
            acc[1][0] += a1 * bv.x; acc[1][1] += a1 * bv.y; acc[1][2] += a1 * bv.z; acc[1][3] += a1 * bv.w;
            acc[2][0] += a2 * bv.x; acc[2][1] += a2 * bv.y; acc[2][2] += a2 * bv.z; acc[2][3] += a2 * bv.w;
            acc[3][0] += a3 * bv.x; acc[3][1] += a3 * bv.y; acc[3][2] += a3 * bv.z; acc[3][3] += a3 * bv.w;
        }
        __syncthreads();
    }
    const int c = tx * 4;
    const int k = c >> 6, d = c & 63;
#pragma unroll
    for (int s = 0; s < 4; s++) {
        int n = n0 + ty * 4 + s;
        float4 o = make_float4(acc[s][0], acc[s][1], acc[s][2], acc[s][3]);
        *(float4*)(g_HW + (k * NN + n) * DD + d) = o;
    }
    // packed half2 copy: rows (2jj, 2jj+1)
    {
        const int jj0 = ((n0 + ty * 4) >> 1);
        uint4 w0, w1;
        w0.x = pack_h2(acc[0][0], acc[1][0]);
        w0.y = pack_h2(acc[0][1], acc[1][1]);
        w0.z = pack_h2(acc[0][2], acc[1][2]);
        w0.w = pack_h2(acc[0][3], acc[1][3]);
        w1.x = pack_h2(acc[2][0], acc[3][0]);
        w1.y = pack_h2(acc[2][1], acc[3][1]);
        w1.z = pack_h2(acc[2][2], acc[3][2]);
        w1.w = pack_h2(acc[2][3], acc[3][3]);
        *(uint4*)(g_HWp + ((size_t)(k * (NN / 2) + jj0) * DD + d))     = w0;
        *(uint4*)(g_HWp + ((size_t)(k * (NN / 2) + jj0 + 1) * DD + d)) = w1;
    }
}

// ------- kernel 2: e1/e2 per (k,n) -> rho + {p2,p52} tables -----------------
__global__ void k_e(const float* __restrict__ a1, const float* __restrict__ a2) {
    __shared__ float a1s[128], a2s[128];
    const int tid = threadIdx.x;
    if (tid < 128) a1s[tid] = a1[tid];
    else           a2s[tid - 128] = a2[tid - 128];
    __syncthreads();
    const int t = blockIdx.x * 256 + tid;     // t = k*8192 + n
    const int k = t >> 13;
    const float* hw = g_HW + (size_t)t * DD;
    const float* A1 = a1s + k * 64;
    const float* A2 = a2s + k * 64;
    float e1 = 0.f, e2 = 0.f;
#pragma unroll
    for (int d4 = 0; d4 < 16; d4++) {
        float4 h = *(const float4*)(hw + d4 * 4);
        e1 += h.x * A1[d4 * 4 + 0] + h.y * A1[d4 * 4 + 1] + h.z * A1[d4 * 4 + 2] + h.w * A1[d4 * 4 + 3];
        e2 += h.x * A2[d4 * 4 + 0] + h.y * A2[d4 * 4 + 1] + h.z * A2[d4 * 4 + 2] + h.w * A2[d4 * 4 + 3];
    }
    g_rho[t] = expf(-0.8f * e1);             // p51/p1
    g_ip2[t] = make_float2(expf(e2), expf(0.2f * e2));
}

// ------- kernel 3: softmax denominators + bitpack A (max-trick) -------------
// Z[j] = p1 * sum_i am * max(p2_i, rho_j * p52_i); q1 = 1/Zacc, q5 = rho*q1.
// Emits q1/q5 as aligned-j-pair half2 words for k_out's fragment build.
__global__ void k_z(const int* __restrict__ A) {
    __shared__ float red[16][8];
    __shared__ float qtmp[2][8][2];
    const int tid = threadIdx.x;
    const int lane = tid & 31, wrp = tid >> 5;
    const int j0 = blockIdx.x * 8;

    float rho[8][2];
#pragma unroll
    for (int j = 0; j < 8; j++) {
        rho[j][0] = g_rho[j0 + j];
        rho[j][1] = g_rho[NN + j0 + j];
    }
    float z[8][2];
#pragma unroll
    for (int j = 0; j < 8; j++) { z[j][0] = 0.f; z[j][1] = 0.f; }

    for (int ci = 0; ci < 32; ci++) {
        const int col = ci * 256 + tid;
        const float2 ip0 = g_ip2[col];
        const float2 ip1 = g_ip2[NN + col];
#pragma unroll
        for (int j = 0; j < 8; j++) {
            int a = A[(size_t)(j0 + j) * NN + col];
            unsigned bal = __ballot_sync(0xffffffffu, a != 0);
            if (lane == 0) g_mask[(j0 + j) * (NN / 32) + ci * 8 + wrp] = bal;
            float am = (a != 0) ? 1.0f : 0.0f;
            z[j][0] += am * fmaxf(ip0.x, rho[j][0] * ip0.y);
            z[j][1] += am * fmaxf(ip1.x, rho[j][1] * ip1.y);
        }
    }
#pragma unroll
    for (int v = 0; v < 16; v++) {
        int j = v >> 1, k = v & 1;
        float val = z[j][k];
        val += __shfl_down_sync(0xffffffffu, val, 16);
        val += __shfl_down_sync(0xffffffffu, val, 8);
        val += __shfl_down_sync(0xffffffffu, val, 4);
        val += __shfl_down_sync(0xffffffffu, val, 2);
        val += __shfl_down_sync(0xffffffffu, val, 1);
        if (lane == 0) red[v][wrp] = val;
    }
    __syncthreads();
    if (tid < 16) {
        int j = tid >> 1, k = tid & 1;
        float s = 0.f;
#pragma unroll
        for (int w = 0; w < 8; w++) s += red[tid][w];
        int gi = k * NN + j0 + j;
        float q1 = 1.0f / s;
        float q5 = g_rho[gi] * q1;
        qtmp[k][j][0] = q1;
        qtmp[k][j][1] = q5;
    }
    __syncthreads();
    if (tid < 8) {
        int k = tid >> 2, p = tid & 3;     // pair p covers j = 2p, 2p+1
        uint2 w;
        w.x = pack_h2(qtmp[k][2 * p][0], qtmp[k][2 * p + 1][0]);
        w.y = pack_h2(qtmp[k][2 * p][1], qtmp[k][2 * p + 1][1]);
        g_jph[k * (NN / 2) + (j0 >> 1) + p] = w;
    }
}

// ------- kernel 4 (f16 mma, i-tile 128 / 8 warps m16n64, pre-packed B) ------
// Weight build fully in f16x2: afr = mask & HMAX2(HMUL2(q1pair,p2), HMUL2(q5pair,p52)).
// Masks via bit-spread + inline-asm PRMT sign-replicate (NOT __byte_perm).
__global__ void __launch_bounds__(256) k_out_mma(float* __restrict__ part) {
    __shared__ unsigned Bs[2][16][72];      // half2{2jj,2jj+1}, [jj][d]
    __shared__ uint2    jtabh[2][16];       // per j-pair: {q1pair, q5pair}
    __shared__ unsigned maskt[2][32][4];    // [j][word]

    const int tid  = threadIdx.x;
    const int lane = tid & 31;
    const int wid  = tid >> 5;
    const int kh   = blockIdx.y;
    const int spl  = blockIdx.z;
    const int i0   = blockIdx.x * 128;
    const int kbase = kh * NN;
    const int kb2   = kh * (NN / 2);
    const int mrow0 = i0 >> 5;
    const int jt0  = spl * (NN / 32 / JSPLIT);     // 32 tiles per split
    const int jt1  = jt0 + (NN / 32 / JSPLIT);

    const int mi = wid;                 // m16 block 0..7
    const int rr = lane >> 2;           // 0..7
    const int cc = lane & 3;            // 0..3
    const int wsel = mi >> 1;           // mask word within 128-i tile
    const int bplo = (mi & 1) * 16 + rr;

    // per-thread i constants as half2 broadcasts
    const float2 fplo = g_ip2[kbase + i0 + mi * 16 + rr];      // {p2, p52} row rr
    const float2 fphi = g_ip2[kbase + i0 + mi * 16 + rr + 8];  // row rr+8
    const unsigned p2lo2  = pack_h2(fplo.x, fplo.x);
    const unsigned p52lo2 = pack_h2(fplo.y, fplo.y);
    const unsigned p2hi2  = pack_h2(fphi.x, fphi.x);
    const unsigned p52hi2 = pack_h2(fphi.y, fphi.y);

    // B-stage coords: thread t stages uint4 at (jj = t>>4, d0 = (t&15)*4)
    const int bjj = tid >> 4;
    const int bd0 = (tid & 15) * 4;

    const int mjj = (tid - 32) >> 2;    // valid for tid in [32,160): 0..31
    const int mword = (tid - 32) & 3;

    uint4 rBu;
    uint2 rJ2;
    unsigned rM = 0;

#define LDG_TILE(JT) do {                                                        \
    const int jj0_ = (JT) * 16;                                                  \
    rBu = *(const uint4*)(g_HWp + ((size_t)(kb2 + jj0_ + bjj) * DD + bd0));      \
    if (tid < 16)                    rJ2 = g_jph[kb2 + jj0_ + tid];              \
    else if (tid >= 32 && tid < 160) rM = g_mask[((JT) * 32 + mjj) * (NN / 32) + mrow0 + mword]; \
} while (0)

#define STS_TILE(BUF) do {                                                       \
    *(uint4*)(&Bs[BUF][bjj][bd0]) = rBu;                                         \
    if (tid < 16)                    jtabh[BUF][tid] = rJ2;                      \
    else if (tid >= 32 && tid < 160) maskt[BUF][mjj][mword] = rM;                \
} while (0)

    float acc[8][4];
#pragma unroll
    for (int nb = 0; nb < 8; nb++)
#pragma unroll
        for (int q = 0; q < 4; q++) acc[nb][q] = 0.f;

    LDG_TILE(jt0);
    STS_TILE(0);
    __syncthreads();

    for (int jt = jt0; jt < jt1; jt++) {
        const int bf = (jt - jt0) & 1;
        if (jt + 1 < jt1) LDG_TILE(jt + 1);

#pragma unroll
        for (int kg = 0; kg < 2; kg++) {            // two k16 groups per 32-j tile
            const int pa = kg * 8 + cc;             // j-pair index (j = 2*pa, 2*pa+1)
            const uint2 qa = jtabh[bf][pa];
            const uint2 qc = jtabh[bf][pa + 4];
            const int ja = 2 * pa;                  // even j, == kg*16 + 2cc
            const unsigned sa = maskt[bf][ja][wsel]     >> bplo;
            const unsigned sb = maskt[bf][ja + 1][wsel] >> bplo;
            const unsigned sc = maskt[bf][ja + 8][wsel] >> bplo;
            const unsigned sd = maskt[bf][ja + 9][wsel] >> bplo;
            // byte MSBs: [sa bit0, sa bit8, sb bit0, sb bit8]
            const unsigned wab = ((sa & 0x101u) << 7) | ((sb & 0x101u) << 23);
            const unsigned wcd = ((sc & 0x101u) << 7) | ((sd & 0x101u) << 23);

            unsigned afr[4];
            afr[0] = hmax2(hmul2(qa.x, p2lo2), hmul2(qa.y, p52lo2))
                     & prmt_repl(wab, 0xAA88u);
            afr[1] = hmax2(hmul2(qa.x, p2hi2), hmul2(qa.y, p52hi2))
                     & prmt_repl(wab, 0xBB99u);
            afr[2] = hmax2(hmul2(qc.x, p2lo2), hmul2(qc.y, p52lo2))
                     & prmt_repl(wcd, 0xAA88u);
            afr[3] = hmax2(hmul2(qc.x, p2hi2), hmul2(qc.y, p52hi2))
                     & prmt_repl(wcd, 0xBB99u);

            const int jjb = kg * 8 + cc;            // half2 column base
#pragma unroll
            for (int nb = 0; nb < 8; nb++) {
                unsigned bfr[2];
                bfr[0] = Bs[bf][jjb][nb * 8 + rr];
                bfr[1] = Bs[bf][jjb + 4][nb * 8 + rr];
                mma_f16(acc[nb], afr, bfr);
            }
        }

        if (jt + 1 < jt1) STS_TILE(bf ^ 1);
        __syncthreads();
    }

    // epilogue: write raw partials to g_part[spl][kh][i][d]
    float* pbase = part + ((size_t)(spl * KH + kh) * NN) * DD;
    const int ilo = i0 + mi * 16 + rr;
#pragma unroll
    for (int nb = 0; nb < 8; nb++) {
        int col = nb * 8 + 2 * cc;
        *(float2*)(pbase + (size_t)ilo * DD + col) = make_float2(acc[nb][0], acc[nb][1]);
        *(float2*)(pbase + (size_t)(ilo + 8) * DD + col) = make_float2(acc[nb][2], acc[nb][3]);
    }
#undef LDG_TILE
#undef STS_TILE
}

// ------- kernel 5: reduce partials + bias + relu ----------------------------
__global__ void k_fin(const float* __restrict__ bias, float* __restrict__ out) {
    const int t = blockIdx.x * 256 + threadIdx.x;   // float4 id over [NN][K*D]
    const int d4 = t & 31;            // float4 within 128-float row
    const int i  = t >> 5;
    const int kh = d4 >> 4;           // head
    const int dd4 = d4 & 15;          // float4 within head
    const size_t pidx = (((size_t)kh * NN + i) * DD + dd4 * 4) / 4;

    const float4* P = (const float4*)g_part;
    const size_t stride4 = (size_t)KH * NN * DD / 4;
    float4 acc = P[pidx];
#pragma unroll
    for (int s = 1; s < JSPLIT; s++) {
        float4 v = P[pidx + (size_t)s * stride4];
        acc.x += v.x; acc.y += v.y; acc.z += v.z; acc.w += v.w;
    }
    float4 bv = *(const float4*)(bias + kh * DD + dd4 * 4);
    float4 o;
    o.x = fmaxf(acc.x + bv.x, 0.f);
    o.y = fmaxf(acc.y + bv.y, 0.f);
    o.z = fmaxf(acc.z + bv.z, 0.f);
    o.w = fmaxf(acc.w + bv.w, 0.f);
    ((float4*)out)[t] = o;
}

// ---------------------------------------------------------------------------
extern "C" void kernel_launch(void* const* d_in, const int* in_sizes, int n_in,
                              void* d_out, int out_size) {
    const float* H  = (const float*)d_in[0];   // [8192,256]
    const int*   A  = (const int*)  d_in[1];   // [8192,8192]
    const float* W  = (const float*)d_in[2];   // [2,256,64]
    const float* b  = (const float*)d_in[3];   // [2,64]
    const float* a1 = (const float*)d_in[4];   // [2,64]
    const float* a2 = (const float*)d_in[5];   // [2,64]
    float* out = (float*)d_out;                // [8192,128]

    float* part;
    cudaGetSymbolAddress((void**)&part, g_part);

    k_hw <<<NN / 32, 256>>>(H, W);
    k_e  <<<(KH * NN) / 256, 256>>>(a1, a2);
    k_z  <<<NN / 8, 256>>>(A);
    k_out_mma<<<dim3(NN / 128, KH, JSPLIT), 256>>>(part);
    k_fin<<<(NN * KH * DD / 4) / 256, 256>>>(b, out);
}

// round 16
// speedup vs baseline: 3.5736x; 1.0845x over previous
#include <cuda_runtime.h>
#include <math.h>
#include <cstdint>

#define NN 8192
#define FF 256
#define DD 64
#define KH 2
#define JSPLIT 8

// ---------------- scratch (static device globals; no allocation) -------------
__device__ float g_HW [KH*NN*DD];        // [k][n][d] fp32 (for k_e)
__device__ unsigned g_HWp[KH*(NN/2)*DD]; // [k][j/2][d] half2{HW[2jj][d],HW[2jj+1][d]}
__device__ float  g_rho[KH*NN];          // exp(-0.8*e1) = p51/p1
__device__ float2 g_ip2[KH*NN];          // {p2=exp(e2), p52=exp(0.2*e2)}
__device__ uint2  g_jph[KH*(NN/2)];      // {half2{q1 even,q1 odd}, half2{q5 even,q5 odd}}
__device__ unsigned g_mask[NN*(NN/32)];  // bitpacked A, row-major [j][i/32]
__device__ float g_part[JSPLIT*KH*NN*DD]; // partial outputs [s][k][i][d]

// ---------------- small PTX helpers (plain sm_80+ PTX) ----------------------
__device__ __forceinline__ unsigned pack_h2(float lo, float hi) {
    unsigned r;
    asm("cvt.rn.f16x2.f32 %0, %1, %2;" : "=r"(r) : "f"(hi), "f"(lo));
    return r;
}
__device__ __forceinline__ unsigned hmul2(unsigned a, unsigned b) {
    unsigned r;
    asm("mul.rn.f16x2 %0, %1, %2;" : "=r"(r) : "r"(a), "r"(b));
    return r;
}
__device__ __forceinline__ unsigned hmax2(unsigned a, unsigned b) {
    unsigned r;
    asm("max.f16x2 %0, %1, %2;" : "=r"(r) : "r"(a), "r"(b));
    return r;
}
// Two-source PRMT with sign-replicate nibbles (bit3). __byte_perm's contract
// covers only 3-bit selectors, so replicate mode must use inline asm.
__device__ __forceinline__ unsigned prmt2(unsigned a, unsigned b, unsigned sel) {
    unsigned r;
    asm("prmt.b32 %0, %1, %2, %3;" : "=r"(r) : "r"(a), "r"(b), "r"(sel));
    return r;
}
__device__ __forceinline__ void mma_f16(float* d, const unsigned* a, const unsigned* bf) {
    asm volatile(
        "mma.sync.aligned.m16n8k16.row.col.f32.f16.f16.f32 "
        "{%0,%1,%2,%3}, {%4,%5,%6,%7}, {%8,%9}, {%0,%1,%2,%3};"
        : "+f"(d[0]), "+f"(d[1]), "+f"(d[2]), "+f"(d[3])
        : "r"(a[0]), "r"(a[1]), "r"(a[2]), "r"(a[3]), "r"(bf[0]), "r"(bf[1]));
}

// ---------------- kernel 1: HW[k][n][d] = sum_f H[n][f] W[k][f][d] ----------
// Also writes the half2-packed copy g_HWp used by k_out.
__global__ void k_hw(const float* __restrict__ H, const float* __restrict__ W) {
    __shared__ float Ws[64][128];
    __shared__ float Hs[32][64];
    const int tid = threadIdx.x;
    const int tx = tid & 31;
    const int ty = tid >> 5;
    const int n0 = blockIdx.x * 32;

    float acc[4][4];
#pragma unroll
    for (int a = 0; a < 4; a++)
#pragma unroll
        for (int b = 0; b < 4; b++) acc[a][b] = 0.f;

    for (int fc = 0; fc < FF; fc += 64) {
#pragma unroll
        for (int q = 0; q < 8; q++) {
            int idx = q * 256 + tid;
            int kk = idx >> 5, c4 = idx & 31;
            int c = c4 * 4;
            int k = c >> 6, d = c & 63;
            float4 v = *(const float4*)(W + k * (FF * DD) + (fc + kk) * DD + d);
            *(float4*)(&Ws[kk][c]) = v;
        }
#pragma unroll
        for (int q = 0; q < 2; q++) {
            int idx = q * 256 + tid;
            int r = idx >> 4, k4 = idx & 15;
            float4 v = *(const float4*)(H + (n0 + r) * FF + fc + k4 * 4);
            *(float4*)(&Hs[r][k4 * 4]) = v;
        }
        __syncthreads();
#pragma unroll 8
        for (int kk = 0; kk < 64; kk++) {
            float4 bv = *(const float4*)(&Ws[kk][tx * 4]);
            float a0 = Hs[ty * 4 + 0][kk];
            float a1 = Hs[ty * 4 + 1][kk];
            float a2 = Hs[ty * 4 + 2][kk];
            float a3 = Hs[ty * 4 + 3][kk];
            acc[0][0] += a0 * bv.x; acc[0][1] += a0 * bv.y; acc[0][2] += a0 * bv.z; acc[0][3] += a0 * bv.w;
            acc[1][0] += a1 * bv.x; acc[1][1] += a1 * bv.y; acc[1][2] += a1 * bv.z; acc[1][3] += a1 * bv.w;
            acc[2][0] += a2 * bv.x; acc[2][1] += a2 * bv.y; acc[2][2] += a2 * bv.z; acc[2][3] += a2 * bv.w;
            acc[3][0] += a3 * bv.x; acc[3][1] += a3 * bv.y; acc[3][2] += a3 * bv.z; acc[3][3] += a3 * bv.w;
        }
        __syncthreads();
    }
    const int c = tx * 4;
    const int k = c >> 6, d = c & 63;
#pragma unroll
    for (int s = 0; s < 4; s++) {
        int n = n0 + ty * 4 + s;
        float4 o = make_float4(acc[s][0], acc[s][1], acc[s][2], acc[s][3]);
        *(float4*)(g_HW + (k * NN + n) * DD + d) = o;
    }
    // packed half2 copy: rows (2jj, 2jj+1)
    {
        const int jj0 = ((n0 + ty * 4) >> 1);
        uint4 w0, w1;
        w0.x = pack_h2(acc[0][0], acc[1][0]);
        w0.y = pack_h2(acc[0][1], acc[1][1]);
        w0.z = pack_h2(acc[0][2], acc[1][2]);
        w0.w = pack_h2(acc[0][3], acc[1][3]);
        w1.x = pack_h2(acc[2][0], acc[3][0]);
        w1.y = pack_h2(acc[2][1], acc[3][1]);
        w1.z = pack_h2(acc[2][2], acc[3][2]);
        w1.w = pack_h2(acc[2][3], acc[3][3]);
        *(uint4*)(g_HWp + ((size_t)(k * (NN / 2) + jj0) * DD + d))     = w0;
        *(uint4*)(g_HWp + ((size_t)(k * (NN / 2) + jj0 + 1) * DD + d)) = w1;
    }
}

// ------- kernel 2: e1/e2 per (k,n) -> rho + {p2,p52} tables -----------------
__global__ void k_e(const float* __restrict__ a1, const float* __restrict__ a2) {
    __shared__ float a1s[128], a2s[128];
    const int tid = threadIdx.x;
    if (tid < 128) a1s[tid] = a1[tid];
    else           a2s[tid - 128] = a2[tid - 128];
    __syncthreads();
    const int t = blockIdx.x * 256 + tid;     // t = k*8192 + n
    const int k = t >> 13;
    const float* hw = g_HW + (size_t)t * DD;
    const float* A1 = a1s + k * 64;
    const float* A2 = a2s + k * 64;
    float e1 = 0.f, e2 = 0.f;
#pragma unroll
    for (int d4 = 0; d4 < 16; d4++) {
        float4 h = *(const float4*)(hw + d4 * 4);
        e1 += h.x * A1[d4 * 4 + 0] + h.y * A1[d4 * 4 + 1] + h.z * A1[d4 * 4 + 2] + h.w * A1[d4 * 4 + 3];
        e2 += h.x * A2[d4 * 4 + 0] + h.y * A2[d4 * 4 + 1] + h.z * A2[d4 * 4 + 2] + h.w * A2[d4 * 4 + 3];
    }
    g_rho[t] = expf(-0.8f * e1);             // p51/p1
    g_ip2[t] = make_float2(expf(e2), expf(0.2f * e2));
}

// ------- kernel 3: softmax denominators + bitpack A (max-trick) -------------
__global__ void k_z(const int* __restrict__ A) {
    __shared__ float red[16][8];
    __shared__ float qtmp[2][8][2];
    const int tid = threadIdx.x;
    const int lane = tid & 31, wrp = tid >> 5;
    const int j0 = blockIdx.x * 8;

    float rho[8][2];
#pragma unroll
    for (int j = 0; j < 8; j++) {
        rho[j][0] = g_rho[j0 + j];
        rho[j][1] = g_rho[NN + j0 + j];
    }
    float z[8][2];
#pragma unroll
    for (int j = 0; j < 8; j++) { z[j][0] = 0.f; z[j][1] = 0.f; }

    for (int ci = 0; ci < 32; ci++) {
        const int col = ci * 256 + tid;
        const float2 ip0 = g_ip2[col];
        const float2 ip1 = g_ip2[NN + col];
#pragma unroll
        for (int j = 0; j < 8; j++) {
            int a = A[(size_t)(j0 + j) * NN + col];
            unsigned bal = __ballot_sync(0xffffffffu, a != 0);
            if (lane == 0) g_mask[(j0 + j) * (NN / 32) + ci * 8 + wrp] = bal;
            float am = (a != 0) ? 1.0f : 0.0f;
            z[j][0] += am * fmaxf(ip0.x, rho[j][0] * ip0.y);
            z[j][1] += am * fmaxf(ip1.x, rho[j][1] * ip1.y);
        }
    }
#pragma unroll
    for (int v = 0; v < 16; v++) {
        int j = v >> 1, k = v & 1;
        float val = z[j][k];
        val += __shfl_down_sync(0xffffffffu, val, 16);
        val += __shfl_down_sync(0xffffffffu, val, 8);
        val += __shfl_down_sync(0xffffffffu, val, 4);
        val += __shfl_down_sync(0xffffffffu, val, 2);
        val += __shfl_down_sync(0xffffffffu, val, 1);
        if (lane == 0) red[v][wrp] = val;
    }
    __syncthreads();
    if (tid < 16) {
        int j = tid >> 1, k = tid & 1;
        float s = 0.f;
#pragma unroll
        for (int w = 0; w < 8; w++) s += red[tid][w];
        int gi = k * NN + j0 + j;
        float q1 = 1.0f / s;
        float q5 = g_rho[gi] * q1;
        qtmp[k][j][0] = q1;
        qtmp[k][j][1] = q5;
    }
    __syncthreads();
    if (tid < 8) {
        int k = tid >> 2, p = tid & 3;     // pair p covers j = 2p, 2p+1
        uint2 w;
        w.x = pack_h2(qtmp[k][2 * p][0], qtmp[k][2 * p + 1][0]);
        w.y = pack_h2(qtmp[k][2 * p][1], qtmp[k][2 * p + 1][1]);
        g_jph[k * (NN / 2) + (j0 >> 1) + p] = w;
    }
}

// ------- kernel 4 (f16 mma, m32n64 warps, i-tile 128 / 4 warps) -------------
// Warp w owns m-blocks (2w, 2w+1): B fragments reused across both m16 halves
// -> B LDS per CTA halves. One mask word carries all 4 row-bits (0/8/16/24
// after >>rr); two-source PRMT sign-replicate builds each half2 AND-mask.
__global__ void __launch_bounds__(128) k_out_mma(float* __restrict__ part) {
    __shared__ __align__(16) unsigned Bs[2][16][72];  // half2{2jj,2jj+1}, [jj][d]
    __shared__ uint2    jtabh[2][16];       // per j-pair: {q1pair, q5pair}
    __shared__ unsigned maskt[2][32][4];    // [j][word]

    const int tid  = threadIdx.x;
    const int lane = tid & 31;
    const int wid  = tid >> 5;              // 0..3
    const int kh   = blockIdx.y;
    const int spl  = blockIdx.z;
    const int i0   = blockIdx.x * 128;
    const int kbase = kh * NN;
    const int kb2   = kh * (NN / 2);
    const int mrow0 = i0 >> 5;
    const int jt0  = spl * (NN / 32 / JSPLIT);     // 32 tiles per split
    const int jt1  = jt0 + (NN / 32 / JSPLIT);

    const int rr = lane >> 2;           // 0..7
    const int cc = lane & 3;            // 0..3

    // per-thread i constants as half2 broadcasts: [block b][half h]
    // row(b,h) = i0 + 32*wid + b*16 + h*8 + rr
    unsigned p2b[2][2], p52b[2][2];
#pragma unroll
    for (int b = 0; b < 2; b++)
#pragma unroll
        for (int h = 0; h < 2; h++) {
            float2 f = g_ip2[kbase + i0 + wid * 32 + b * 16 + h * 8 + rr];
            p2b[b][h]  = pack_h2(f.x, f.x);
            p52b[b][h] = pack_h2(f.y, f.y);
        }

    // B-stage coords: thread t stages 2 uint4 at (jj = t>>3, words (t&7)*8 ..)
    const int bjj = tid >> 3;
    const int bu0 = (tid & 7) * 8;
    // mask coords: all 128 threads stage one word
    const int mjj = tid >> 2;
    const int mword = tid & 3;

    uint4 rBu0, rBu1;
    uint2 rJ2;
    unsigned rM = 0;

#define LDG_TILE(JT) do {                                                        \
    const int jj0_ = (JT) * 16;                                                  \
    const unsigned* src_ = g_HWp + ((size_t)(kb2 + jj0_ + bjj) * DD + bu0);      \
    rBu0 = *(const uint4*)(src_);                                                \
    rBu1 = *(const uint4*)(src_ + 4);                                            \
    rM = g_mask[((JT) * 32 + mjj) * (NN / 32) + mrow0 + mword];                  \
    if (tid < 16) rJ2 = g_jph[kb2 + jj0_ + tid];                                 \
} while (0)

#define STS_TILE(BUF) do {                                                       \
    *(uint4*)(&Bs[BUF][bjj][bu0])     = rBu0;                                    \
    *(uint4*)(&Bs[BUF][bjj][bu0 + 4]) = rBu1;                                    \
    maskt[BUF][mjj][mword] = rM;                                                 \
    if (tid < 16) jtabh[BUF][tid] = rJ2;                                         \
} while (0)

    float acc[2][8][4];
#pragma unroll
    for (int b = 0; b < 2; b++)
#pragma unroll
        for (int nb = 0; nb < 8; nb++)
#pragma unroll
            for (int q = 0; q < 4; q++) acc[b][nb][q] = 0.f;

    LDG_TILE(jt0);
    STS_TILE(0);
    __syncthreads();

    for (int jt = jt0; jt < jt1; jt++) {
        const int bf = (jt - jt0) & 1;
        if (jt + 1 < jt1) LDG_TILE(jt + 1);

#pragma unroll
        for (int kg = 0; kg < 2; kg++) {            // two k16 groups per 32-j tile
            const int pa = kg * 8 + cc;             // j-pair index (j = 2*pa, 2*pa+1)
            const uint2 qa = jtabh[bf][pa];
            const uint2 qc = jtabh[bf][pa + 4];
            const int ja = 2 * pa;                  // even j, == kg*16 + 2cc
            // mask word wid covers this warp's 32 rows; bits 0/8/16/24 after >>rr
            const unsigned ta = ((maskt[bf][ja][wid]     >> rr) << 7) & 0x80808080u;
            const unsigned tb = ((maskt[bf][ja + 1][wid] >> rr) << 7) & 0x80808080u;
            const unsigned tc = ((maskt[bf][ja + 8][wid] >> rr) << 7) & 0x80808080u;
            const unsigned td = ((maskt[bf][ja + 9][wid] >> rr) << 7) & 0x80808080u;

            // weight values shared per (pair, block, half)
            unsigned va[2][2], vc[2][2];
#pragma unroll
            for (int b = 0; b < 2; b++)
#pragma unroll
                for (int h = 0; h < 2; h++) {
                    va[b][h] = hmax2(hmul2(qa.x, p2b[b][h]), hmul2(qa.y, p52b[b][h]));
                    vc[b][h] = hmax2(hmul2(qc.x, p2b[b][h]), hmul2(qc.y, p52b[b][h]));
                }

            // masks: bytes {b0=row rr, b1=rr+8, b2=rr+16, b3=rr+24}
            unsigned afr[2][4];
            afr[0][0] = va[0][0] & prmt2(ta, tb, 0xCC88u);
            afr[0][1] = va[0][1] & prmt2(ta, tb, 0xDD99u);
            afr[0][2] = vc[0][0] & prmt2(tc, td, 0xCC88u);
            afr[0][3] = vc[0][1] & prmt2(tc, td, 0xDD99u);
            afr[1][0] = va[1][0] & prmt2(ta, tb, 0xEEAAu);
            afr[1][1] = va[1][1] & prmt2(ta, tb, 0xFFBBu);
            afr[1][2] = vc[1][0] & prmt2(tc, td, 0xEEAAu);
            afr[1][3] = vc[1][1] & prmt2(tc, td, 0xFFBBu);

            const int jjb = kg * 8 + cc;            // half2 column base
#pragma unroll
            for (int nb = 0; nb < 8; nb++) {
                unsigned bfr[2];
                bfr[0] = Bs[bf][jjb][nb * 8 + rr];
                bfr[1] = Bs[bf][jjb + 4][nb * 8 + rr];
                mma_f16(acc[0][nb], afr[0], bfr);
                mma_f16(acc[1][nb], afr[1], bfr);
            }
        }

        if (jt + 1 < jt1) STS_TILE(bf ^ 1);
        __syncthreads();
    }

    // epilogue: write raw partials to g_part[spl][kh][i][d]
    float* pbase = part + ((size_t)(spl * KH + kh) * NN) * DD;
#pragma unroll
    for (int b = 0; b < 2; b++) {
        const int ilo = i0 + wid * 32 + b * 16 + rr;
#pragma unroll
        for (int nb = 0; nb < 8; nb++) {
            int col = nb * 8 + 2 * cc;
            *(float2*)(pbase + (size_t)ilo * DD + col) =
                make_float2(acc[b][nb][0], acc[b][nb][1]);
            *(float2*)(pbase + (size_t)(ilo + 8) * DD + col) =
                make_float2(acc[b][nb][2], acc[b][nb][3]);
        }
    }
#undef LDG_TILE
#undef STS_TILE
}

// ------- kernel 5: reduce partials + bias + relu ----------------------------
__global__ void k_fin(const float* __restrict__ bias, float* __restrict__ out) {
    const int t = blockIdx.x * 256 + threadIdx.x;   // float4 id over [NN][K*D]
    const int d4 = t & 31;            // float4 within 128-float row
    const int i  = t >> 5;
    const int kh = d4 >> 4;           // head
    const int dd4 = d4 & 15;          // float4 within head
    const size_t pidx = (((size_t)kh * NN + i) * DD + dd4 * 4) / 4;

    const float4* P = (const float4*)g_part;
    const size_t stride4 = (size_t)KH * NN * DD / 4;
    float4 acc = P[pidx];
#pragma unroll
    for (int s = 1; s < JSPLIT; s++) {
        float4 v = P[pidx + (size_t)s * stride4];
        acc.x += v.x; acc.y += v.y; acc.z += v.z; acc.w += v.w;
    }
    float4 bv = *(const float4*)(bias + kh * DD + dd4 * 4);
    float4 o;
    o.x = fmaxf(acc.x + bv.x, 0.f);
    o.y = fmaxf(acc.y + bv.y, 0.f);
    o.z = fmaxf(acc.z + bv.z, 0.f);
    o.w = fmaxf(acc.w + bv.w, 0.f);
    ((float4*)out)[t] = o;
}

// ---------------------------------------------------------------------------
extern "C" void kernel_launch(void* const* d_in, const int* in_sizes, int n_in,
                              void* d_out, int out_size) {
    const float* H  = (const float*)d_in[0];   // [8192,256]
    const int*   A  = (const int*)  d_in[1];   // [8192,8192]
    const float* W  = (const float*)d_in[2];   // [2,256,64]
    const float* b  = (const float*)d_in[3];   // [2,64]
    const float* a1 = (const float*)d_in[4];   // [2,64]
    const float* a2 = (const float*)d_in[5];   // [2,64]
    float* out = (float*)d_out;                // [8192,128]

    float* part;
    cudaGetSymbolAddress((void**)&part, g_part);

    k_hw <<<NN / 32, 256>>>(H, W);
    k_e  <<<(KH * NN) / 256, 256>>>(a1, a2);
    k_z  <<<NN / 8, 256>>>(A);
    k_out_mma<<<dim3(NN / 128, KH, JSPLIT), 128>>>(part);
    k_fin<<<(NN * KH * DD / 4) / 256, 256>>>(b, out);
}